// round 1
// baseline (speedup 1.0000x reference)
#include <cuda_runtime.h>
#include <cuda_fp16.h>
#include <cstddef>

// Problem constants (fixed by the dataset)
#define NTOK 4096   // B*L
#define HDIM 2048
#define EEXP 8
#define DFF  8192

// Scratch: device globals (no runtime allocation allowed)
__device__ __align__(256) float g_h1[(size_t)NTOK * DFF];   // gelu(x@w1), 134 MB
__device__ __align__(256) float g_probs[NTOK * EEXP];

// ---------------------------------------------------------------------------
// Router: logits = x @ router_w  (K=2048, E=8), softmax, fp16 round-trip
// One block per token row.
// ---------------------------------------------------------------------------
__global__ __launch_bounds__(256) void router_kernel(const float* __restrict__ x,
                                                     const float* __restrict__ rw,
                                                     float* __restrict__ probs)
{
    int n = blockIdx.x;
    int tid = threadIdx.x;
    float acc[EEXP] = {0.f, 0.f, 0.f, 0.f, 0.f, 0.f, 0.f, 0.f};
    const float* xr = x + (size_t)n * HDIM;
    for (int k = tid; k < HDIM; k += 256) {
        float xv = xr[k];
        const float4* r4 = reinterpret_cast<const float4*>(rw + (size_t)k * EEXP);
        float4 a = r4[0];
        float4 b = r4[1];
        acc[0] = fmaf(xv, a.x, acc[0]);
        acc[1] = fmaf(xv, a.y, acc[1]);
        acc[2] = fmaf(xv, a.z, acc[2]);
        acc[3] = fmaf(xv, a.w, acc[3]);
        acc[4] = fmaf(xv, b.x, acc[4]);
        acc[5] = fmaf(xv, b.y, acc[5]);
        acc[6] = fmaf(xv, b.z, acc[6]);
        acc[7] = fmaf(xv, b.w, acc[7]);
    }
    __shared__ float sbuf[EEXP][256];
#pragma unroll
    for (int e = 0; e < EEXP; e++) sbuf[e][tid] = acc[e];
    __syncthreads();
    for (int s = 128; s > 0; s >>= 1) {
        if (tid < s) {
#pragma unroll
            for (int e = 0; e < EEXP; e++) sbuf[e][tid] += sbuf[e][tid + s];
        }
        __syncthreads();
    }
    if (tid == 0) {
        float l[EEXP];
        float m = -1e30f;
#pragma unroll
        for (int e = 0; e < EEXP; e++) { l[e] = sbuf[e][0]; m = fmaxf(m, l[e]); }
        float s = 0.f;
#pragma unroll
        for (int e = 0; e < EEXP; e++) { l[e] = expf(l[e] - m); s += l[e]; }
        float inv = 1.0f / s;
#pragma unroll
        for (int e = 0; e < EEXP; e++) {
            // match reference: softmax in fp32, cast fp16, back to fp32
            probs[n * EEXP + e] = __half2float(__float2half(l[e] * inv));
        }
    }
}

// ---------------------------------------------------------------------------
// SGEMM: C[M,N] = op(A[M,K] @ B[K,N]); op = tanh-GELU if GELU template flag.
// 128x128 tile, BK=8, 8x8 per thread, 256 threads. All dims divide evenly.
// ---------------------------------------------------------------------------
#define BM 128
#define BN 128
#define BK 8
#define TM 8
#define TN 8

__device__ __forceinline__ float gelu_tanh(float v)
{
    // JAX default gelu (approximate=True)
    float inner = 0.7978845608028654f * (v + 0.044715f * v * v * v);
    return 0.5f * v * (1.0f + tanhf(inner));
}

template <bool GELU>
__global__ __launch_bounds__(256) void sgemm_kernel(const float* __restrict__ A,
                                                    const float* __restrict__ B,
                                                    float* __restrict__ C,
                                                    int M, int N, int K)
{
    __shared__ float As[BK][BM];
    __shared__ float Bs[BK][BN];

    const int bx = blockIdx.x;   // N direction
    const int by = blockIdx.y;   // M direction
    const int tid = threadIdx.x;
    const int tx = tid & 15;     // N direction (8 cols each)
    const int ty = tid >> 4;     // M direction (8 rows each)

    // global-load assignments
    const int a_row = tid >> 1;          // 0..127
    const int a_col = (tid & 1) * 4;     // 0 or 4
    const int b_row = tid >> 5;          // 0..7
    const int b_col = (tid & 31) * 4;    // 0..124

    const float* A_ptr = A + (size_t)(by * BM + a_row) * K + a_col;
    const float* B_ptr = B + (size_t)b_row * N + bx * BN + b_col;

    float acc[TM][TN];
#pragma unroll
    for (int i = 0; i < TM; i++)
#pragma unroll
        for (int j = 0; j < TN; j++) acc[i][j] = 0.f;

    float a_frag[TM], b_frag[TN];

    for (int k0 = 0; k0 < K; k0 += BK) {
        float4 a4 = *reinterpret_cast<const float4*>(A_ptr);
        float4 b4 = *reinterpret_cast<const float4*>(B_ptr);
        As[a_col + 0][a_row] = a4.x;
        As[a_col + 1][a_row] = a4.y;
        As[a_col + 2][a_row] = a4.z;
        As[a_col + 3][a_row] = a4.w;
        *reinterpret_cast<float4*>(&Bs[b_row][b_col]) = b4;
        __syncthreads();

#pragma unroll
        for (int k = 0; k < BK; k++) {
#pragma unroll
            for (int i = 0; i < TM; i += 4) {
                float4 t = *reinterpret_cast<const float4*>(&As[k][ty * TM + i]);
                a_frag[i + 0] = t.x; a_frag[i + 1] = t.y;
                a_frag[i + 2] = t.z; a_frag[i + 3] = t.w;
            }
#pragma unroll
            for (int j = 0; j < TN; j += 4) {
                float4 t = *reinterpret_cast<const float4*>(&Bs[k][tx * TN + j]);
                b_frag[j + 0] = t.x; b_frag[j + 1] = t.y;
                b_frag[j + 2] = t.z; b_frag[j + 3] = t.w;
            }
#pragma unroll
            for (int i = 0; i < TM; i++)
#pragma unroll
                for (int j = 0; j < TN; j++)
                    acc[i][j] = fmaf(a_frag[i], b_frag[j], acc[i][j]);
        }
        __syncthreads();
        A_ptr += BK;
        B_ptr += (size_t)BK * N;
    }

    float* Cp = C + (size_t)(by * BM + ty * TM) * N + bx * BN + tx * TN;
#pragma unroll
    for (int i = 0; i < TM; i++) {
        float4 v0, v1;
        if (GELU) {
            v0.x = gelu_tanh(acc[i][0]); v0.y = gelu_tanh(acc[i][1]);
            v0.z = gelu_tanh(acc[i][2]); v0.w = gelu_tanh(acc[i][3]);
            v1.x = gelu_tanh(acc[i][4]); v1.y = gelu_tanh(acc[i][5]);
            v1.z = gelu_tanh(acc[i][6]); v1.w = gelu_tanh(acc[i][7]);
        } else {
            v0.x = acc[i][0]; v0.y = acc[i][1]; v0.z = acc[i][2]; v0.w = acc[i][3];
            v1.x = acc[i][4]; v1.y = acc[i][5]; v1.z = acc[i][6]; v1.w = acc[i][7];
        }
        *reinterpret_cast<float4*>(Cp + (size_t)i * N)     = v0;
        *reinterpret_cast<float4*>(Cp + (size_t)i * N + 4) = v1;
    }
}

// ---------------------------------------------------------------------------
// MoE: out[n,h] += sum_e probs[n,e] * (cb[nibble]*std[n,e,h/512] + mean[n,e,h/512])
// One block per token; each thread owns 8 consecutive h (4 packed ints/expert).
// ---------------------------------------------------------------------------
__global__ __launch_bounds__(256) void moe_kernel(const int* __restrict__ nf4,
                                                  const float* __restrict__ mean,
                                                  const float* __restrict__ stdv,
                                                  const float* __restrict__ cbg,
                                                  const float* __restrict__ probs,
                                                  float* __restrict__ out)
{
    __shared__ float cb[16];
    __shared__ float pr[EEXP];
    const int tid = threadIdx.x;
    const int n = blockIdx.x;
    if (tid < 16) cb[tid] = cbg[tid];
    if (tid < EEXP) pr[tid] = probs[n * EEXP + tid];
    __syncthreads();

    const int h0 = tid * 8;
    const int b = h0 >> 9;   // 512-element quant block, constant over this thread's strip
    float acc[8] = {0.f, 0.f, 0.f, 0.f, 0.f, 0.f, 0.f, 0.f};

    const int4* base = reinterpret_cast<const int4*>(nf4 + (size_t)n * EEXP * (HDIM / 2)) + tid;
#pragma unroll
    for (int e = 0; e < EEXP; e++) {
        float p = pr[e];
        float sc = p * stdv[((size_t)n * EEXP + e) * 4 + b];
        float bi = p * mean[((size_t)n * EEXP + e) * 4 + b];
        int4 v = base[e * (HDIM / 2 / 4)];
        int vs[4] = {v.x, v.y, v.z, v.w};
#pragma unroll
        for (int j = 0; j < 4; j++) {
            acc[2 * j]     += fmaf(cb[vs[j] & 15], sc, bi);         // low nibble -> even h
            acc[2 * j + 1] += fmaf(cb[(vs[j] >> 4) & 15], sc, bi);  // high nibble -> odd h
        }
    }

    float4* o = reinterpret_cast<float4*>(out + (size_t)n * HDIM + h0);
    float4 o0 = o[0], o1 = o[1];
    o0.x += acc[0]; o0.y += acc[1]; o0.z += acc[2]; o0.w += acc[3];
    o1.x += acc[4]; o1.y += acc[5]; o1.z += acc[6]; o1.w += acc[7];
    o[0] = o0; o[1] = o1;
}

// ---------------------------------------------------------------------------
// Launch
// inputs: 0:x 1:router_w 2:nf4 3:mean 4:std 5:codebook 6:w1 7:w2 ; out fp32
// ---------------------------------------------------------------------------
extern "C" void kernel_launch(void* const* d_in, const int* in_sizes, int n_in,
                              void* d_out, int out_size)
{
    const float* x        = (const float*)d_in[0];
    const float* router_w = (const float*)d_in[1];
    const int*   nf4      = (const int*)d_in[2];
    const float* mean     = (const float*)d_in[3];
    const float* stdv     = (const float*)d_in[4];
    const float* codebook = (const float*)d_in[5];
    const float* w1       = (const float*)d_in[6];
    const float* w2       = (const float*)d_in[7];
    float* out = (float*)d_out;

    float* h1 = nullptr;
    float* probs = nullptr;
    cudaGetSymbolAddress((void**)&h1, g_h1);
    cudaGetSymbolAddress((void**)&probs, g_probs);

    // router probs (independent of GEMMs, tiny)
    router_kernel<<<NTOK, 256>>>(x, router_w, probs);

    // h1 = gelu(x @ w1)   [4096 x 8192]
    sgemm_kernel<true><<<dim3(DFF / BN, NTOK / BM), 256>>>(x, w1, h1, NTOK, DFF, HDIM);

    // out = h1 @ w2       [4096 x 2048]  (beta = 0, fully overwrites d_out)
    sgemm_kernel<false><<<dim3(HDIM / BN, NTOK / BM), 256>>>(h1, w2, out, NTOK, HDIM, DFF);

    // out += weighted NF4 expert mix
    moe_kernel<<<NTOK, 256>>>(nf4, mean, stdv, codebook, probs, out);
}

// round 3
// speedup vs baseline: 3.2701x; 3.2701x over previous
#include <cuda_runtime.h>
#include <cuda_fp16.h>
#include <cstdint>
#include <cstddef>

// Problem constants
#define NTOK 4096   // B*L
#define HDIM 2048
#define EEXP 8
#define DFF  8192

// ---------------------------------------------------------------------------
// Scratch (device globals; no runtime allocation allowed)
// ---------------------------------------------------------------------------
__device__ __align__(256) __half g_xh[(size_t)NTOK * HDIM];
__device__ __align__(256) __half g_xl[(size_t)NTOK * HDIM];
__device__ __align__(256) __half g_w1h[(size_t)DFF * HDIM];   // transposed [DFF, HDIM]
__device__ __align__(256) __half g_w1l[(size_t)DFF * HDIM];
__device__ __align__(256) __half g_w2h[(size_t)HDIM * DFF];   // transposed [HDIM, DFF]
__device__ __align__(256) __half g_w2l[(size_t)HDIM * DFF];
__device__ __align__(256) __half g_h1h[(size_t)NTOK * DFF];
__device__ __align__(256) __half g_h1l[(size_t)NTOK * DFF];
__device__ __align__(256) float g_probs[NTOK * EEXP];

// ---------------------------------------------------------------------------
// PTX helpers (family-agnostic: sm_80+ ops only — NO tcgen05 on this toolchain)
// ---------------------------------------------------------------------------
__device__ __forceinline__ uint32_t smem_u32(const void* p) {
    uint32_t a;
    asm("{ .reg .u64 t; cvta.to.shared.u64 t, %1; cvt.u32.u64 %0, t; }" : "=r"(a) : "l"(p));
    return a;
}
__device__ __forceinline__ void cp_async16(uint32_t dst, const void* src) {
    asm volatile("cp.async.cg.shared.global [%0], [%1], 16;" :: "r"(dst), "l"(src));
}
__device__ __forceinline__ void cp_commit() {
    asm volatile("cp.async.commit_group;" ::: "memory");
}
template <int N>
__device__ __forceinline__ void cp_wait() {
    asm volatile("cp.async.wait_group %0;" :: "n"(N) : "memory");
}
__device__ __forceinline__ void ldsm_x4(uint32_t* r, uint32_t addr) {
    asm volatile("ldmatrix.sync.aligned.m8n8.x4.shared.b16 {%0,%1,%2,%3}, [%4];"
                 : "=r"(r[0]), "=r"(r[1]), "=r"(r[2]), "=r"(r[3]) : "r"(addr));
}
__device__ __forceinline__ void mma_16816(float* d, const uint32_t* a, const uint32_t* b) {
    asm volatile("mma.sync.aligned.m16n8k16.row.col.f32.f16.f16.f32 "
                 "{%0,%1,%2,%3}, {%4,%5,%6,%7}, {%8,%9}, {%0,%1,%2,%3};"
                 : "+f"(d[0]), "+f"(d[1]), "+f"(d[2]), "+f"(d[3])
                 : "r"(a[0]), "r"(a[1]), "r"(a[2]), "r"(a[3]), "r"(b[0]), "r"(b[1]));
}

// ---------------------------------------------------------------------------
// Conversion kernels: fp32 -> fp16 hi/lo split (2-term; dropped lo*lo ~2^-22)
// ---------------------------------------------------------------------------
__global__ __launch_bounds__(256) void split_kernel(const float* __restrict__ in,
                                                    __half* __restrict__ oh,
                                                    __half* __restrict__ ol,
                                                    int n)
{
    int i = blockIdx.x * 256 + threadIdx.x;
    if (i < n) {
        float v = in[i];
        __half h = __float2half_rn(v);
        oh[i] = h;
        ol[i] = __float2half_rn(v - __half2float(h));
    }
}

// w [K,N] fp32 row-major -> oh/ol [N,K] fp16 (transposed, K-major)
__global__ __launch_bounds__(256) void transpose_split_kernel(const float* __restrict__ w,
                                                              __half* __restrict__ oh,
                                                              __half* __restrict__ ol,
                                                              int K, int N)
{
    __shared__ float t[32][33];
    const int n0 = blockIdx.x * 32;
    const int k0 = blockIdx.y * 32;
    const int tx = threadIdx.x & 31;
    const int ty = threadIdx.x >> 5;   // 0..7
#pragma unroll
    for (int r = 0; r < 4; r++) {
        int kk = ty + r * 8;
        t[kk][tx] = w[(size_t)(k0 + kk) * N + n0 + tx];
    }
    __syncthreads();
#pragma unroll
    for (int r = 0; r < 4; r++) {
        int nn = ty + r * 8;
        float v = t[tx][nn];  // = w[k0+tx][n0+nn]
        __half h = __float2half_rn(v);
        size_t o = (size_t)(n0 + nn) * K + k0 + tx;
        oh[o] = h;
        ol[o] = __float2half_rn(v - __half2float(h));
    }
}

// ---------------------------------------------------------------------------
// HGEMM via mma.sync: C[M,N] = op(A @ B^T)
// A [M,K] fp16 hi/lo, B [N,K] fp16 hi/lo. 3 products: hh + hl + lh (fp32 acc).
// CTA tile 128x128, BK=64 halves (128B rows, SW128 xor swizzle), 2-stage
// cp.async double buffer, 8 warps (2x4), warp tile 64x32.
// GELU=true: tanh-GELU then fp16 hi/lo re-split into Ch/Cl. Else fp32 Cf.
// ---------------------------------------------------------------------------
#define TILE_B   16384            // 128 rows x 128 B
#define STAGE_B  (4 * TILE_B)     // Ah, Al, Bh, Bl

__device__ __forceinline__ float gelu_tanh(float v)
{
    float inner = 0.7978845608028654f * (v + 0.044715f * v * v * v);
    return 0.5f * v * (1.0f + tanhf(inner));
}

template <bool GELU>
__global__ __launch_bounds__(256, 1) void hgemm_kernel(const __half* __restrict__ Ah,
                                                       const __half* __restrict__ Al,
                                                       const __half* __restrict__ Bh,
                                                       const __half* __restrict__ Bl,
                                                       __half* __restrict__ Ch,
                                                       __half* __restrict__ Cl,
                                                       float* __restrict__ Cf,
                                                       int N, int K)
{
    extern __shared__ __align__(1024) char smem[];
    const uint32_t sm0 = smem_u32(smem);

    const int tid = threadIdx.x;
    const int lane = tid & 31;
    const int wid = tid >> 5;
    const int wm = wid & 1;        // M warp coord (2)
    const int wn = wid >> 1;       // N warp coord (4)
    const int bx = blockIdx.x;     // N tile
    const int by = blockIdx.y;     // M tile
    const int NK = K >> 6;         // K / 64

    // ldmatrix lane decomposition
    const int g = lane >> 3;
    const int lr = lane & 7;
    const int a_row = ((g & 1) << 3) + lr;   // A: matrices (rows, rows+8) x (k, k+8)
    const int a_c = g >> 1;
    const int b_row = ((g >> 1) << 3) + lr;  // B: matrices (k, k+8) x (rows, rows+8)
    const int b_c = g & 1;

    // global load coords: thread t loads rows r+32*it, 16B chunk c
    const int ld_r = tid >> 3;     // 0..31
    const int ld_c = tid & 7;      // 16B chunk in 128B row
    const __half* gbase[4] = {
        Ah + (size_t)(by * 128 + ld_r) * K + ld_c * 8,
        Al + (size_t)(by * 128 + ld_r) * K + ld_c * 8,
        Bh + (size_t)(bx * 128 + ld_r) * K + ld_c * 8,
        Bl + (size_t)(bx * 128 + ld_r) * K + ld_c * 8 };

    auto load_stage = [&](int j, int slot) {
        uint32_t sb = sm0 + slot * STAGE_B;
        size_t ko = (size_t)j * 64;   // halves
#pragma unroll
        for (int t = 0; t < 4; t++) {
            const __half* src = gbase[t] + ko;
            uint32_t db = sb + t * TILE_B;
#pragma unroll
            for (int it = 0; it < 4; it++) {
                int row = ld_r + it * 32;
                uint32_t d = db + row * 128 + (((ld_c ^ (row & 7))) << 4);
                cp_async16(d, src + (size_t)it * 32 * K);
            }
        }
    };

    float acc[4][4][4];
#pragma unroll
    for (int mt = 0; mt < 4; mt++)
#pragma unroll
        for (int nt = 0; nt < 4; nt++)
#pragma unroll
            for (int q = 0; q < 4; q++) acc[mt][nt][q] = 0.f;

    load_stage(0, 0);
    cp_commit();

    for (int i = 0; i < NK; i++) {
        if (i + 1 < NK) {
            load_stage(i + 1, (i + 1) & 1);
            cp_commit();
            cp_wait<1>();
        } else {
            cp_wait<0>();
        }
        __syncthreads();

        const uint32_t sb = sm0 + (i & 1) * STAGE_B;
        const uint32_t aBase = sb + (wm * 64 + a_row) * 128;
        const uint32_t bBase = sb + 2 * TILE_B + (wn * 32 + b_row) * 128;

#pragma unroll
        for (int ks = 0; ks < 4; ks++) {
            const int cb = ks * 2;
            uint32_t ah[4][4], al[4][4], bh2[2][4], bl2[2][4];
#pragma unroll
            for (int mt = 0; mt < 4; mt++) {
                uint32_t ad = aBase + mt * 16 * 128 + (((cb + a_c) ^ lr) << 4);
                ldsm_x4(ah[mt], ad);
                ldsm_x4(al[mt], ad + TILE_B);
            }
#pragma unroll
            for (int nt2 = 0; nt2 < 2; nt2++) {
                uint32_t bd = bBase + nt2 * 16 * 128 + (((cb + b_c) ^ lr) << 4);
                ldsm_x4(bh2[nt2], bd);
                ldsm_x4(bl2[nt2], bd + TILE_B);
            }
#pragma unroll
            for (int mt = 0; mt < 4; mt++) {
#pragma unroll
                for (int nt = 0; nt < 4; nt++) {
                    const uint32_t* bhf = &bh2[nt >> 1][(nt & 1) * 2];
                    const uint32_t* blf = &bl2[nt >> 1][(nt & 1) * 2];
                    mma_16816(acc[mt][nt], ah[mt], bhf);
                    mma_16816(acc[mt][nt], ah[mt], blf);
                    mma_16816(acc[mt][nt], al[mt], bhf);
                }
            }
        }
        __syncthreads();
    }

    // Epilogue. acc element map: d0,d1 = (row qr, col 2qc,+1); d2,d3 = (row qr+8)
    const int qr = lane >> 2;
    const int qc = lane & 3;
#pragma unroll
    for (int mt = 0; mt < 4; mt++) {
        const size_t m0 = (size_t)by * 128 + wm * 64 + mt * 16 + qr;
#pragma unroll
        for (int nt = 0; nt < 4; nt++) {
            const size_t n0 = (size_t)bx * 128 + wn * 32 + nt * 8 + qc * 2;
            const float* d = acc[mt][nt];
            if (GELU) {
                float g0 = gelu_tanh(d[0]);
                float g1 = gelu_tanh(d[1]);
                float g2 = gelu_tanh(d[2]);
                float g3 = gelu_tanh(d[3]);
                __half h0 = __float2half_rn(g0), h1 = __float2half_rn(g1);
                __half h2 = __float2half_rn(g2), h3 = __float2half_rn(g3);
                __half l0 = __float2half_rn(g0 - __half2float(h0));
                __half l1 = __float2half_rn(g1 - __half2float(h1));
                __half l2 = __float2half_rn(g2 - __half2float(h2));
                __half l3 = __float2half_rn(g3 - __half2float(h3));
                *reinterpret_cast<__half2*>(Ch + m0 * N + n0)       = __halves2half2(h0, h1);
                *reinterpret_cast<__half2*>(Ch + (m0 + 8) * N + n0) = __halves2half2(h2, h3);
                *reinterpret_cast<__half2*>(Cl + m0 * N + n0)       = __halves2half2(l0, l1);
                *reinterpret_cast<__half2*>(Cl + (m0 + 8) * N + n0) = __halves2half2(l2, l3);
            } else {
                float2 v0; v0.x = d[0]; v0.y = d[1];
                float2 v1; v1.x = d[2]; v1.y = d[3];
                *reinterpret_cast<float2*>(Cf + m0 * N + n0)       = v0;
                *reinterpret_cast<float2*>(Cf + (m0 + 8) * N + n0) = v1;
            }
        }
    }
}

// ---------------------------------------------------------------------------
// Router: logits = x @ router_w (K=2048, E=8), softmax, fp16 round-trip
// ---------------------------------------------------------------------------
__global__ __launch_bounds__(256) void router_kernel(const float* __restrict__ x,
                                                     const float* __restrict__ rw,
                                                     float* __restrict__ probs)
{
    int n = blockIdx.x;
    int tid = threadIdx.x;
    float acc[EEXP] = {0.f, 0.f, 0.f, 0.f, 0.f, 0.f, 0.f, 0.f};
    const float* xr = x + (size_t)n * HDIM;
    for (int k = tid; k < HDIM; k += 256) {
        float xv = xr[k];
        const float4* r4 = reinterpret_cast<const float4*>(rw + (size_t)k * EEXP);
        float4 a = r4[0];
        float4 b = r4[1];
        acc[0] = fmaf(xv, a.x, acc[0]); acc[1] = fmaf(xv, a.y, acc[1]);
        acc[2] = fmaf(xv, a.z, acc[2]); acc[3] = fmaf(xv, a.w, acc[3]);
        acc[4] = fmaf(xv, b.x, acc[4]); acc[5] = fmaf(xv, b.y, acc[5]);
        acc[6] = fmaf(xv, b.z, acc[6]); acc[7] = fmaf(xv, b.w, acc[7]);
    }
    __shared__ float sbuf[EEXP][256];
#pragma unroll
    for (int e = 0; e < EEXP; e++) sbuf[e][tid] = acc[e];
    __syncthreads();
    for (int s = 128; s > 0; s >>= 1) {
        if (tid < s) {
#pragma unroll
            for (int e = 0; e < EEXP; e++) sbuf[e][tid] += sbuf[e][tid + s];
        }
        __syncthreads();
    }
    if (tid == 0) {
        float l[EEXP];
        float mmax = -1e30f;
#pragma unroll
        for (int e = 0; e < EEXP; e++) { l[e] = sbuf[e][0]; mmax = fmaxf(mmax, l[e]); }
        float s = 0.f;
#pragma unroll
        for (int e = 0; e < EEXP; e++) { l[e] = expf(l[e] - mmax); s += l[e]; }
        float inv = 1.0f / s;
#pragma unroll
        for (int e = 0; e < EEXP; e++)
            probs[n * EEXP + e] = __half2float(__float2half(l[e] * inv));
    }
}

// ---------------------------------------------------------------------------
// MoE: out[n,h] += sum_e probs[n,e] * (cb[nibble]*std + mean)
// ---------------------------------------------------------------------------
__global__ __launch_bounds__(256) void moe_kernel(const int* __restrict__ nf4,
                                                  const float* __restrict__ mean,
                                                  const float* __restrict__ stdv,
                                                  const float* __restrict__ cbg,
                                                  const float* __restrict__ probs,
                                                  float* __restrict__ out)
{
    __shared__ float cb[16];
    __shared__ float pr[EEXP];
    const int tid = threadIdx.x;
    const int n = blockIdx.x;
    if (tid < 16) cb[tid] = cbg[tid];
    if (tid < EEXP) pr[tid] = probs[n * EEXP + tid];
    __syncthreads();

    const int h0 = tid * 8;
    const int b = h0 >> 9;
    float acc[8] = {0.f, 0.f, 0.f, 0.f, 0.f, 0.f, 0.f, 0.f};

    const int4* base = reinterpret_cast<const int4*>(nf4 + (size_t)n * EEXP * (HDIM / 2)) + tid;
#pragma unroll
    for (int e = 0; e < EEXP; e++) {
        float p = pr[e];
        float sc = p * stdv[((size_t)n * EEXP + e) * 4 + b];
        float bi = p * mean[((size_t)n * EEXP + e) * 4 + b];
        int4 v = base[e * (HDIM / 2 / 4)];
        int vs[4] = {v.x, v.y, v.z, v.w};
#pragma unroll
        for (int j = 0; j < 4; j++) {
            acc[2 * j]     += fmaf(cb[vs[j] & 15], sc, bi);
            acc[2 * j + 1] += fmaf(cb[(vs[j] >> 4) & 15], sc, bi);
        }
    }

    float4* o = reinterpret_cast<float4*>(out + (size_t)n * HDIM + h0);
    float4 o0 = o[0], o1 = o[1];
    o0.x += acc[0]; o0.y += acc[1]; o0.z += acc[2]; o0.w += acc[3];
    o1.x += acc[4]; o1.y += acc[5]; o1.z += acc[6]; o1.w += acc[7];
    o[0] = o0; o[1] = o1;
}

// ---------------------------------------------------------------------------
// Launch. inputs: 0:x 1:router_w 2:nf4 3:mean 4:std 5:codebook 6:w1 7:w2
// ---------------------------------------------------------------------------
extern "C" void kernel_launch(void* const* d_in, const int* in_sizes, int n_in,
                              void* d_out, int out_size)
{
    const float* x        = (const float*)d_in[0];
    const float* router_w = (const float*)d_in[1];
    const int*   nf4      = (const int*)d_in[2];
    const float* mean     = (const float*)d_in[3];
    const float* stdv     = (const float*)d_in[4];
    const float* codebook = (const float*)d_in[5];
    const float* w1       = (const float*)d_in[6];
    const float* w2       = (const float*)d_in[7];
    float* out = (float*)d_out;

    __half *xh, *xl, *w1h, *w1l, *w2h, *w2l, *h1h, *h1l;
    float* probs;
    cudaGetSymbolAddress((void**)&xh,  g_xh);
    cudaGetSymbolAddress((void**)&xl,  g_xl);
    cudaGetSymbolAddress((void**)&w1h, g_w1h);
    cudaGetSymbolAddress((void**)&w1l, g_w1l);
    cudaGetSymbolAddress((void**)&w2h, g_w2h);
    cudaGetSymbolAddress((void**)&w2l, g_w2l);
    cudaGetSymbolAddress((void**)&h1h, g_h1h);
    cudaGetSymbolAddress((void**)&h1l, g_h1l);
    cudaGetSymbolAddress((void**)&probs, g_probs);

    const int smem_bytes = 2 * STAGE_B;   // 128 KB
    cudaFuncSetAttribute(hgemm_kernel<true>,  cudaFuncAttributeMaxDynamicSharedMemorySize, smem_bytes);
    cudaFuncSetAttribute(hgemm_kernel<false>, cudaFuncAttributeMaxDynamicSharedMemorySize, smem_bytes);

    // conversions
    split_kernel<<<(NTOK * HDIM) / 256, 256>>>(x, xh, xl, NTOK * HDIM);
    transpose_split_kernel<<<dim3(DFF / 32, HDIM / 32), 256>>>(w1, w1h, w1l, HDIM, DFF);
    transpose_split_kernel<<<dim3(HDIM / 32, DFF / 32), 256>>>(w2, w2h, w2l, DFF, HDIM);

    // router (independent)
    router_kernel<<<NTOK, 256>>>(x, router_w, probs);

    // h1 = gelu(x @ w1) -> fp16 hi/lo   [4096 x 8192]
    hgemm_kernel<true><<<dim3(DFF / 128, NTOK / 128), 256, smem_bytes>>>(
        xh, xl, w1h, w1l, h1h, h1l, nullptr, DFF, HDIM);

    // out = h1 @ w2                     [4096 x 2048]
    hgemm_kernel<false><<<dim3(HDIM / 128, NTOK / 128), 256, smem_bytes>>>(
        h1h, h1l, w2h, w2l, nullptr, nullptr, out, HDIM, DFF);

    // out += weighted NF4 expert mix
    moe_kernel<<<NTOK, 256>>>(nf4, mean, stdv, codebook, probs, out);
}

// round 4
// speedup vs baseline: 3.3017x; 1.0097x over previous
#include <cuda_runtime.h>
#include <cuda_fp16.h>
#include <cstdint>
#include <cstddef>

// Problem constants
#define NTOK 4096   // B*L
#define HDIM 2048
#define EEXP 8
#define DFF  8192

// ---------------------------------------------------------------------------
// Scratch (device globals; no runtime allocation allowed)
// ---------------------------------------------------------------------------
__device__ __align__(256) __half g_xh[(size_t)NTOK * HDIM];
__device__ __align__(256) __half g_xl[(size_t)NTOK * HDIM];
__device__ __align__(256) __half g_w1h[(size_t)DFF * HDIM];   // transposed [DFF, HDIM]
__device__ __align__(256) __half g_w1l[(size_t)DFF * HDIM];
__device__ __align__(256) __half g_w2h[(size_t)HDIM * DFF];   // transposed [HDIM, DFF]
__device__ __align__(256) __half g_w2l[(size_t)HDIM * DFF];
__device__ __align__(256) __half g_h1h[(size_t)NTOK * DFF];
__device__ __align__(256) __half g_h1l[(size_t)NTOK * DFF];
__device__ __align__(256) float g_probs[NTOK * EEXP];

// ---------------------------------------------------------------------------
// PTX helpers (family-agnostic sm_80+ ops; tcgen05 unavailable on this toolchain)
// ---------------------------------------------------------------------------
__device__ __forceinline__ uint32_t smem_u32(const void* p) {
    uint32_t a;
    asm("{ .reg .u64 t; cvta.to.shared.u64 t, %1; cvt.u32.u64 %0, t; }" : "=r"(a) : "l"(p));
    return a;
}
__device__ __forceinline__ void cp_async16(uint32_t dst, const void* src) {
    asm volatile("cp.async.cg.shared.global [%0], [%1], 16;" :: "r"(dst), "l"(src));
}
__device__ __forceinline__ void cp_commit() {
    asm volatile("cp.async.commit_group;" ::: "memory");
}
template <int N>
__device__ __forceinline__ void cp_wait() {
    asm volatile("cp.async.wait_group %0;" :: "n"(N) : "memory");
}
__device__ __forceinline__ void ldsm_x4(uint32_t* r, uint32_t addr) {
    asm volatile("ldmatrix.sync.aligned.m8n8.x4.shared.b16 {%0,%1,%2,%3}, [%4];"
                 : "=r"(r[0]), "=r"(r[1]), "=r"(r[2]), "=r"(r[3]) : "r"(addr));
}
__device__ __forceinline__ void mma_16816(float* d, const uint32_t* a, const uint32_t* b) {
    asm volatile("mma.sync.aligned.m16n8k16.row.col.f32.f16.f16.f32 "
                 "{%0,%1,%2,%3}, {%4,%5,%6,%7}, {%8,%9}, {%0,%1,%2,%3};"
                 : "+f"(d[0]), "+f"(d[1]), "+f"(d[2]), "+f"(d[3])
                 : "r"(a[0]), "r"(a[1]), "r"(a[2]), "r"(a[3]), "r"(b[0]), "r"(b[1]));
}

// ---------------------------------------------------------------------------
// Conversion kernels: fp32 -> fp16 hi/lo split (2-term; dropped lo*lo ~2^-22)
// ---------------------------------------------------------------------------
__global__ __launch_bounds__(256) void split_kernel(const float* __restrict__ in,
                                                    __half* __restrict__ oh,
                                                    __half* __restrict__ ol,
                                                    int n)
{
    int i = blockIdx.x * 256 + threadIdx.x;
    if (i < n) {
        float v = in[i];
        __half h = __float2half_rn(v);
        oh[i] = h;
        ol[i] = __float2half_rn(v - __half2float(h));
    }
}

// w [K,N] fp32 row-major -> oh/ol [N,K] fp16 (transposed, K-major)
__global__ __launch_bounds__(256) void transpose_split_kernel(const float* __restrict__ w,
                                                              __half* __restrict__ oh,
                                                              __half* __restrict__ ol,
                                                              int K, int N)
{
    __shared__ float t[32][33];
    const int n0 = blockIdx.x * 32;
    const int k0 = blockIdx.y * 32;
    const int tx = threadIdx.x & 31;
    const int ty = threadIdx.x >> 5;   // 0..7
#pragma unroll
    for (int r = 0; r < 4; r++) {
        int kk = ty + r * 8;
        t[kk][tx] = w[(size_t)(k0 + kk) * N + n0 + tx];
    }
    __syncthreads();
#pragma unroll
    for (int r = 0; r < 4; r++) {
        int nn = ty + r * 8;
        float v = t[tx][nn];  // = w[k0+tx][n0+nn]
        __half h = __float2half_rn(v);
        size_t o = (size_t)(n0 + nn) * K + k0 + tx;
        oh[o] = h;
        ol[o] = __float2half_rn(v - __half2float(h));
    }
}

// ---------------------------------------------------------------------------
// HGEMM via mma.sync: C[M,N] = op(A @ B^T)
// A [M,K] fp16 hi/lo, B [N,K] fp16 hi/lo. 3 products: hh + hl + lh (fp32 acc).
// CTA tile 128x128, BK=64 halves (128B swizzled rows), 3-stage cp.async
// pipeline, register double-buffered fragments, 8 warps (2x4), warp 64x32.
// 1-D grid with GROUP_N raster swizzle for L2 reuse.
// GELU=true: tanh-GELU then fp16 hi/lo re-split into Ch/Cl. Else fp32 Cf.
// ---------------------------------------------------------------------------
#define TILE_B   16384            // 128 rows x 128 B
#define STAGE_B  (4 * TILE_B)     // Ah, Al, Bh, Bl
#define NSTAGE   3
#define GROUP_N  16

__device__ __forceinline__ float gelu_tanh(float v)
{
    float inner = 0.7978845608028654f * (v + 0.044715f * v * v * v);
    return 0.5f * v * (1.0f + tanhf(inner));
}

template <bool GELU>
__global__ __launch_bounds__(256, 1) void hgemm_kernel(const __half* __restrict__ Ah,
                                                       const __half* __restrict__ Al,
                                                       const __half* __restrict__ Bh,
                                                       const __half* __restrict__ Bl,
                                                       __half* __restrict__ Ch,
                                                       __half* __restrict__ Cl,
                                                       float* __restrict__ Cf,
                                                       int N, int K)
{
    extern __shared__ __align__(1024) char smem[];
    const uint32_t sm0 = smem_u32(smem);

    const int tid = threadIdx.x;
    const int lane = tid & 31;
    const int wid = tid >> 5;
    const int wm = wid & 1;        // M warp coord (2)
    const int wn = wid >> 1;       // N warp coord (4)
    const int NK = K >> 6;         // K / 64

    // raster swizzle: consecutive CTAs walk M within a GROUP_N-wide N band
    const int tilesN = N >> 7;
    const int per_group = GROUP_N * (NTOK >> 7);
    const int grp = blockIdx.x / per_group;
    const int rem = blockIdx.x % per_group;
    const int bx = grp * GROUP_N + (rem % GROUP_N);
    const int by = rem / GROUP_N;
    (void)tilesN;

    // ldmatrix lane decomposition
    const int g = lane >> 3;
    const int lr = lane & 7;
    const int a_row = ((g & 1) << 3) + lr;
    const int a_c = g >> 1;
    const int b_row = ((g >> 1) << 3) + lr;
    const int b_c = g & 1;

    // global load coords: thread t loads rows ld_r+32*it, 16B chunk ld_c
    const int ld_r = tid >> 3;     // 0..31
    const int ld_c = tid & 7;      // 16B chunk in 128B row
    const __half* gbase[4] = {
        Ah + (size_t)(by * 128 + ld_r) * K + ld_c * 8,
        Al + (size_t)(by * 128 + ld_r) * K + ld_c * 8,
        Bh + (size_t)(bx * 128 + ld_r) * K + ld_c * 8,
        Bl + (size_t)(bx * 128 + ld_r) * K + ld_c * 8 };

    auto load_stage = [&](int j, int slot) {
        uint32_t sb = sm0 + slot * STAGE_B;
        size_t ko = (size_t)j * 64;   // halves
#pragma unroll
        for (int t = 0; t < 4; t++) {
            const __half* src = gbase[t] + ko;
            uint32_t db = sb + t * TILE_B;
#pragma unroll
            for (int it = 0; it < 4; it++) {
                int row = ld_r + it * 32;
                uint32_t d = db + row * 128 + (((ld_c ^ (row & 7))) << 4);
                cp_async16(d, src + (size_t)it * 32 * K);
            }
        }
    };

    float acc[4][4][4];
#pragma unroll
    for (int mt = 0; mt < 4; mt++)
#pragma unroll
        for (int nt = 0; nt < 4; nt++)
#pragma unroll
            for (int q = 0; q < 4; q++) acc[mt][nt][q] = 0.f;

    load_stage(0, 0); cp_commit();
    load_stage(1, 1); cp_commit();

    uint32_t ah[2][4][4], al[2][4][4], bh[2][2][4], bl[2][2][4];

    for (int i = 0; i < NK; i++) {
        cp_wait<1>();                 // chunk i resident (i+1 may be in flight)
        __syncthreads();              // all warps done reading slot (i+2)%3==(i-1)%3

        // prefetch chunk i+2 into the slot just freed
        if (i + 2 < NK) load_stage(i + 2, (i + 2) % 3);
        cp_commit();

        const uint32_t sb = sm0 + (i % 3) * STAGE_B;
        const uint32_t aBase = sb + (wm * 64 + a_row) * 128;
        const uint32_t bBase = sb + 2 * TILE_B + (wn * 32 + b_row) * 128;

        // fragment load for k-step ks into buffer b
        auto load_frags = [&](int ks, int b) {
            const int cb = ks * 2;
#pragma unroll
            for (int mt = 0; mt < 4; mt++) {
                uint32_t ad = aBase + mt * 2048 + (((cb + a_c) ^ lr) << 4);
                ldsm_x4(ah[b][mt], ad);
                ldsm_x4(al[b][mt], ad + TILE_B);
            }
#pragma unroll
            for (int nt2 = 0; nt2 < 2; nt2++) {
                uint32_t bd = bBase + nt2 * 2048 + (((cb + b_c) ^ lr) << 4);
                ldsm_x4(bh[b][nt2], bd);
                ldsm_x4(bl[b][nt2], bd + TILE_B);
            }
        };

        load_frags(0, 0);
#pragma unroll
        for (int ks = 0; ks < 4; ks++) {
            const int cur = ks & 1;
            if (ks < 3) load_frags(ks + 1, cur ^ 1);
#pragma unroll
            for (int mt = 0; mt < 4; mt++) {
#pragma unroll
                for (int nt = 0; nt < 4; nt++) {
                    const uint32_t* bhf = &bh[cur][nt >> 1][(nt & 1) * 2];
                    const uint32_t* blf = &bl[cur][nt >> 1][(nt & 1) * 2];
                    mma_16816(acc[mt][nt], ah[cur][mt], bhf);
                    mma_16816(acc[mt][nt], ah[cur][mt], blf);
                    mma_16816(acc[mt][nt], al[cur][mt], bhf);
                }
            }
        }
    }

    // Epilogue. acc map: d0,d1 = (row qr, cols 2qc,2qc+1); d2,d3 = row qr+8
    const int qr = lane >> 2;
    const int qc = lane & 3;
#pragma unroll
    for (int mt = 0; mt < 4; mt++) {
        const size_t m0 = (size_t)by * 128 + wm * 64 + mt * 16 + qr;
#pragma unroll
        for (int nt = 0; nt < 4; nt++) {
            const size_t n0 = (size_t)bx * 128 + wn * 32 + nt * 8 + qc * 2;
            const float* d = acc[mt][nt];
            if (GELU) {
                float g0 = gelu_tanh(d[0]);
                float g1 = gelu_tanh(d[1]);
                float g2 = gelu_tanh(d[2]);
                float g3 = gelu_tanh(d[3]);
                __half h0 = __float2half_rn(g0), h1 = __float2half_rn(g1);
                __half h2 = __float2half_rn(g2), h3 = __float2half_rn(g3);
                __half l0 = __float2half_rn(g0 - __half2float(h0));
                __half l1 = __float2half_rn(g1 - __half2float(h1));
                __half l2 = __float2half_rn(g2 - __half2float(h2));
                __half l3 = __float2half_rn(g3 - __half2float(h3));
                *reinterpret_cast<__half2*>(Ch + m0 * N + n0)       = __halves2half2(h0, h1);
                *reinterpret_cast<__half2*>(Ch + (m0 + 8) * N + n0) = __halves2half2(h2, h3);
                *reinterpret_cast<__half2*>(Cl + m0 * N + n0)       = __halves2half2(l0, l1);
                *reinterpret_cast<__half2*>(Cl + (m0 + 8) * N + n0) = __halves2half2(l2, l3);
            } else {
                float2 v0; v0.x = d[0]; v0.y = d[1];
                float2 v1; v1.x = d[2]; v1.y = d[3];
                *reinterpret_cast<float2*>(Cf + m0 * N + n0)       = v0;
                *reinterpret_cast<float2*>(Cf + (m0 + 8) * N + n0) = v1;
            }
        }
    }
}

// ---------------------------------------------------------------------------
// Router: logits = x @ router_w (K=2048, E=8), softmax, fp16 round-trip
// ---------------------------------------------------------------------------
__global__ __launch_bounds__(256) void router_kernel(const float* __restrict__ x,
                                                     const float* __restrict__ rw,
                                                     float* __restrict__ probs)
{
    int n = blockIdx.x;
    int tid = threadIdx.x;
    float acc[EEXP] = {0.f, 0.f, 0.f, 0.f, 0.f, 0.f, 0.f, 0.f};
    const float* xr = x + (size_t)n * HDIM;
    for (int k = tid; k < HDIM; k += 256) {
        float xv = xr[k];
        const float4* r4 = reinterpret_cast<const float4*>(rw + (size_t)k * EEXP);
        float4 a = r4[0];
        float4 b = r4[1];
        acc[0] = fmaf(xv, a.x, acc[0]); acc[1] = fmaf(xv, a.y, acc[1]);
        acc[2] = fmaf(xv, a.z, acc[2]); acc[3] = fmaf(xv, a.w, acc[3]);
        acc[4] = fmaf(xv, b.x, acc[4]); acc[5] = fmaf(xv, b.y, acc[5]);
        acc[6] = fmaf(xv, b.z, acc[6]); acc[7] = fmaf(xv, b.w, acc[7]);
    }
    __shared__ float sbuf[EEXP][256];
#pragma unroll
    for (int e = 0; e < EEXP; e++) sbuf[e][tid] = acc[e];
    __syncthreads();
    for (int s = 128; s > 0; s >>= 1) {
        if (tid < s) {
#pragma unroll
            for (int e = 0; e < EEXP; e++) sbuf[e][tid] += sbuf[e][tid + s];
        }
        __syncthreads();
    }
    if (tid == 0) {
        float l[EEXP];
        float mmax = -1e30f;
#pragma unroll
        for (int e = 0; e < EEXP; e++) { l[e] = sbuf[e][0]; mmax = fmaxf(mmax, l[e]); }
        float s = 0.f;
#pragma unroll
        for (int e = 0; e < EEXP; e++) { l[e] = expf(l[e] - mmax); s += l[e]; }
        float inv = 1.0f / s;
#pragma unroll
        for (int e = 0; e < EEXP; e++)
            probs[n * EEXP + e] = __half2float(__float2half(l[e] * inv));
    }
}

// ---------------------------------------------------------------------------
// MoE: out[n,h] += sum_e probs[n,e] * (cb[nibble]*std + mean)
// ---------------------------------------------------------------------------
__global__ __launch_bounds__(256) void moe_kernel(const int* __restrict__ nf4,
                                                  const float* __restrict__ mean,
                                                  const float* __restrict__ stdv,
                                                  const float* __restrict__ cbg,
                                                  const float* __restrict__ probs,
                                                  float* __restrict__ out)
{
    __shared__ float cb[16];
    __shared__ float pr[EEXP];
    const int tid = threadIdx.x;
    const int n = blockIdx.x;
    if (tid < 16) cb[tid] = cbg[tid];
    if (tid < EEXP) pr[tid] = probs[n * EEXP + tid];
    __syncthreads();

    const int h0 = tid * 8;
    const int b = h0 >> 9;
    float acc[8] = {0.f, 0.f, 0.f, 0.f, 0.f, 0.f, 0.f, 0.f};

    const int4* base = reinterpret_cast<const int4*>(nf4 + (size_t)n * EEXP * (HDIM / 2)) + tid;
#pragma unroll
    for (int e = 0; e < EEXP; e++) {
        float p = pr[e];
        float sc = p * stdv[((size_t)n * EEXP + e) * 4 + b];
        float bi = p * mean[((size_t)n * EEXP + e) * 4 + b];
        int4 v = base[e * (HDIM / 2 / 4)];
        int vs[4] = {v.x, v.y, v.z, v.w};
#pragma unroll
        for (int j = 0; j < 4; j++) {
            acc[2 * j]     += fmaf(cb[vs[j] & 15], sc, bi);
            acc[2 * j + 1] += fmaf(cb[(vs[j] >> 4) & 15], sc, bi);
        }
    }

    float4* o = reinterpret_cast<float4*>(out + (size_t)n * HDIM + h0);
    float4 o0 = o[0], o1 = o[1];
    o0.x += acc[0]; o0.y += acc[1]; o0.z += acc[2]; o0.w += acc[3];
    o1.x += acc[4]; o1.y += acc[5]; o1.z += acc[6]; o1.w += acc[7];
    o[0] = o0; o[1] = o1;
}

// ---------------------------------------------------------------------------
// Launch. inputs: 0:x 1:router_w 2:nf4 3:mean 4:std 5:codebook 6:w1 7:w2
// ---------------------------------------------------------------------------
extern "C" void kernel_launch(void* const* d_in, const int* in_sizes, int n_in,
                              void* d_out, int out_size)
{
    const float* x        = (const float*)d_in[0];
    const float* router_w = (const float*)d_in[1];
    const int*   nf4      = (const int*)d_in[2];
    const float* mean     = (const float*)d_in[3];
    const float* stdv     = (const float*)d_in[4];
    const float* codebook = (const float*)d_in[5];
    const float* w1       = (const float*)d_in[6];
    const float* w2       = (const float*)d_in[7];
    float* out = (float*)d_out;

    __half *xh, *xl, *w1h, *w1l, *w2h, *w2l, *h1h, *h1l;
    float* probs;
    cudaGetSymbolAddress((void**)&xh,  g_xh);
    cudaGetSymbolAddress((void**)&xl,  g_xl);
    cudaGetSymbolAddress((void**)&w1h, g_w1h);
    cudaGetSymbolAddress((void**)&w1l, g_w1l);
    cudaGetSymbolAddress((void**)&w2h, g_w2h);
    cudaGetSymbolAddress((void**)&w2l, g_w2l);
    cudaGetSymbolAddress((void**)&h1h, g_h1h);
    cudaGetSymbolAddress((void**)&h1l, g_h1l);
    cudaGetSymbolAddress((void**)&probs, g_probs);

    const int smem_bytes = NSTAGE * STAGE_B;   // 192 KB
    cudaFuncSetAttribute(hgemm_kernel<true>,  cudaFuncAttributeMaxDynamicSharedMemorySize, smem_bytes);
    cudaFuncSetAttribute(hgemm_kernel<false>, cudaFuncAttributeMaxDynamicSharedMemorySize, smem_bytes);

    // conversions
    split_kernel<<<(NTOK * HDIM) / 256, 256>>>(x, xh, xl, NTOK * HDIM);
    transpose_split_kernel<<<dim3(DFF / 32, HDIM / 32), 256>>>(w1, w1h, w1l, HDIM, DFF);
    transpose_split_kernel<<<dim3(HDIM / 32, DFF / 32), 256>>>(w2, w2h, w2l, DFF, HDIM);

    // router (independent)
    router_kernel<<<NTOK, 256>>>(x, router_w, probs);

    // h1 = gelu(x @ w1) -> fp16 hi/lo   [4096 x 8192]
    hgemm_kernel<true><<<(DFF / 128) * (NTOK / 128), 256, smem_bytes>>>(
        xh, xl, w1h, w1l, h1h, h1l, nullptr, DFF, HDIM);

    // out = h1 @ w2                     [4096 x 2048]
    hgemm_kernel<false><<<(HDIM / 128) * (NTOK / 128), 256, smem_bytes>>>(
        h1h, h1l, w2h, w2l, nullptr, nullptr, out, HDIM, DFF);

    // out += weighted NF4 expert mix
    moe_kernel<<<NTOK, 256>>>(nf4, mean, stdv, codebook, probs, out);
}

// round 6
// speedup vs baseline: 3.4200x; 1.0358x over previous
#include <cuda_runtime.h>
#include <cuda_fp16.h>
#include <cstdint>
#include <cstddef>

// Problem constants
#define NTOK 4096   // B*L
#define HDIM 2048
#define EEXP 8
#define DFF  8192

// ---------------------------------------------------------------------------
// Scratch (device globals; no runtime allocation allowed)
// ---------------------------------------------------------------------------
__device__ __align__(256) __half g_xh[(size_t)NTOK * HDIM];
__device__ __align__(256) __half g_xl[(size_t)NTOK * HDIM];
__device__ __align__(256) __half g_w1h[(size_t)DFF * HDIM];   // transposed [DFF, HDIM]
__device__ __align__(256) __half g_w1l[(size_t)DFF * HDIM];
__device__ __align__(256) __half g_w2h[(size_t)HDIM * DFF];   // transposed [HDIM, DFF]
__device__ __align__(256) __half g_w2l[(size_t)HDIM * DFF];
__device__ __align__(256) __half g_h1h[(size_t)NTOK * DFF];
__device__ __align__(256) __half g_h1l[(size_t)NTOK * DFF];
__device__ __align__(256) float g_probs[NTOK * EEXP];

// ---------------------------------------------------------------------------
// PTX helpers (family-agnostic sm_80+ ops; tcgen05 unavailable on this toolchain)
// ---------------------------------------------------------------------------
__device__ __forceinline__ uint32_t smem_u32(const void* p) {
    uint32_t a;
    asm("{ .reg .u64 t; cvta.to.shared.u64 t, %1; cvt.u32.u64 %0, t; }" : "=r"(a) : "l"(p));
    return a;
}
__device__ __forceinline__ void cp_async16(uint32_t dst, const void* src) {
    asm volatile("cp.async.cg.shared.global [%0], [%1], 16;" :: "r"(dst), "l"(src));
}
__device__ __forceinline__ void cp_commit() {
    asm volatile("cp.async.commit_group;" ::: "memory");
}
template <int N>
__device__ __forceinline__ void cp_wait() {
    asm volatile("cp.async.wait_group %0;" :: "n"(N) : "memory");
}
__device__ __forceinline__ void ldsm_x4(uint32_t* r, uint32_t addr) {
    asm volatile("ldmatrix.sync.aligned.m8n8.x4.shared.b16 {%0,%1,%2,%3}, [%4];"
                 : "=r"(r[0]), "=r"(r[1]), "=r"(r[2]), "=r"(r[3]) : "r"(addr));
}
__device__ __forceinline__ void mma_16816(float* d, const uint32_t* a, const uint32_t* b) {
    asm volatile("mma.sync.aligned.m16n8k16.row.col.f32.f16.f16.f32 "
                 "{%0,%1,%2,%3}, {%4,%5,%6,%7}, {%8,%9}, {%0,%1,%2,%3};"
                 : "+f"(d[0]), "+f"(d[1]), "+f"(d[2]), "+f"(d[3])
                 : "r"(a[0]), "r"(a[1]), "r"(a[2]), "r"(a[3]), "r"(b[0]), "r"(b[1]));
}

// ---------------------------------------------------------------------------
// Conversion kernels: fp32 -> fp16 hi/lo split (2-term; dropped lo*lo ~2^-22)
// ---------------------------------------------------------------------------
__global__ __launch_bounds__(256) void split_kernel(const float* __restrict__ in,
                                                    __half* __restrict__ oh,
                                                    __half* __restrict__ ol,
                                                    int n)
{
    int i = blockIdx.x * 256 + threadIdx.x;
    if (i < n) {
        float v = in[i];
        __half h = __float2half_rn(v);
        oh[i] = h;
        ol[i] = __float2half_rn(v - __half2float(h));
    }
}

// w [K,N] fp32 row-major -> oh/ol [N,K] fp16 (transposed, K-major)
__global__ __launch_bounds__(256) void transpose_split_kernel(const float* __restrict__ w,
                                                              __half* __restrict__ oh,
                                                              __half* __restrict__ ol,
                                                              int K, int N)
{
    __shared__ float t[32][33];
    const int n0 = blockIdx.x * 32;
    const int k0 = blockIdx.y * 32;
    const int tx = threadIdx.x & 31;
    const int ty = threadIdx.x >> 5;   // 0..7
#pragma unroll
    for (int r = 0; r < 4; r++) {
        int kk = ty + r * 8;
        t[kk][tx] = w[(size_t)(k0 + kk) * N + n0 + tx];
    }
    __syncthreads();
#pragma unroll
    for (int r = 0; r < 4; r++) {
        int nn = ty + r * 8;
        float v = t[tx][nn];  // = w[k0+tx][n0+nn]
        __half h = __float2half_rn(v);
        size_t o = (size_t)(n0 + nn) * K + k0 + tx;
        oh[o] = h;
        ol[o] = __float2half_rn(v - __half2float(h));
    }
}

// ---------------------------------------------------------------------------
// HGEMM via mma.sync: C[M,N] = op(A @ B^T)
// A [M,K] fp16 hi/lo, B [N,K] fp16 hi/lo. 3 products: hh + hl + lh (fp32 acc).
// CTA tile 256x128 (M x N), BK=64 halves, 2-stage cp.async pipeline.
// 8 warps arranged 4(M) x 2(N); warp tile 64x64 -> ldmatrix bytes per MMA cut
// 1.5x vs 64x32 to get under the 128 B/cyc smem crossbar.
// GELU=true: tanh-GELU then fp16 hi/lo re-split into Ch/Cl. Else fp32 Cf.
// ---------------------------------------------------------------------------
#define A_T_B   32768             // A tile bytes per term: 256 rows x 128 B
#define B_T_B   16384             // B tile bytes per term: 128 rows x 128 B
#define STAGE_B (2 * A_T_B + 2 * B_T_B)   // 96 KB
#define OFF_AL  A_T_B
#define OFF_BH  (2 * A_T_B)
#define OFF_BL  (2 * A_T_B + B_T_B)
#define GROUP_N 16

__device__ __forceinline__ float gelu_tanh(float v)
{
    float inner = 0.7978845608028654f * (v + 0.044715f * v * v * v);
    return 0.5f * v * (1.0f + tanhf(inner));
}

template <bool GELU>
__global__ __launch_bounds__(256, 1) void hgemm_kernel(const __half* __restrict__ Ah,
                                                       const __half* __restrict__ Al,
                                                       const __half* __restrict__ Bh,
                                                       const __half* __restrict__ Bl,
                                                       __half* __restrict__ Ch,
                                                       __half* __restrict__ Cl,
                                                       float* __restrict__ Cf,
                                                       int N, int K)
{
    extern __shared__ __align__(1024) char smem[];
    const uint32_t sm0 = smem_u32(smem);

    const int tid = threadIdx.x;
    const int lane = tid & 31;
    const int wid = tid >> 5;
    const int wm = wid & 3;        // M warp coord (4) -> 64 rows each
    const int wn = wid >> 2;       // N warp coord (2) -> 64 cols each
    const int NK = K >> 6;         // K / 64

    // raster swizzle: consecutive CTAs walk M within a GROUP_N-wide N band
    const int tilesM = NTOK / 256;
    const int per_group = GROUP_N * tilesM;
    const int grp = blockIdx.x / per_group;
    const int rem = blockIdx.x % per_group;
    const int bx = grp * GROUP_N + (rem % GROUP_N);
    const int by = rem / GROUP_N;

    // ldmatrix lane decomposition
    const int g = lane >> 3;
    const int lr = lane & 7;
    const int a_row = ((g & 1) << 3) + lr;
    const int a_c = g >> 1;
    const int b_row = ((g >> 1) << 3) + lr;
    const int b_c = g & 1;

    // global load coords: thread t loads rows ld_r+32*it, 16B chunk ld_c
    const int ld_r = tid >> 3;     // 0..31
    const int ld_c = tid & 7;      // 16B chunk in 128B row
    const __half* gA[2] = {
        Ah + (size_t)(by * 256 + ld_r) * K + ld_c * 8,
        Al + (size_t)(by * 256 + ld_r) * K + ld_c * 8 };
    const __half* gB[2] = {
        Bh + (size_t)(bx * 128 + ld_r) * K + ld_c * 8,
        Bl + (size_t)(bx * 128 + ld_r) * K + ld_c * 8 };

    auto load_stage = [&](int j, int slot) {
        uint32_t sb = sm0 + slot * STAGE_B;
        size_t ko = (size_t)j * 64;   // halves
#pragma unroll
        for (int t = 0; t < 2; t++) {
            const __half* src = gA[t] + ko;
            uint32_t db = sb + t * A_T_B;
#pragma unroll
            for (int it = 0; it < 8; it++) {          // 256 rows / 32
                int row = ld_r + it * 32;
                uint32_t d = db + row * 128 + ((ld_c ^ (row & 7)) << 4);
                cp_async16(d, src + (size_t)it * 32 * K);
            }
        }
#pragma unroll
        for (int t = 0; t < 2; t++) {
            const __half* src = gB[t] + ko;
            uint32_t db = sb + OFF_BH + t * B_T_B;
#pragma unroll
            for (int it = 0; it < 4; it++) {          // 128 rows / 32
                int row = ld_r + it * 32;
                uint32_t d = db + row * 128 + ((ld_c ^ (row & 7)) << 4);
                cp_async16(d, src + (size_t)it * 32 * K);
            }
        }
    };

    float acc[4][8][4];
#pragma unroll
    for (int mt = 0; mt < 4; mt++)
#pragma unroll
        for (int nt = 0; nt < 8; nt++)
#pragma unroll
            for (int q = 0; q < 4; q++) acc[mt][nt][q] = 0.f;

    load_stage(0, 0);
    cp_commit();

    uint32_t ah[4][4], al[4][4], bh[4][4], bl[4][4];

    for (int i = 0; i < NK; i++) {
        cp_wait<0>();                 // chunk i resident
        __syncthreads();              // readers of slot (i+1)&1 (chunk i-1) done

        if (i + 1 < NK) {             // prefetch next chunk, overlapped w/ compute
            load_stage(i + 1, (i + 1) & 1);
            cp_commit();
        }

        const uint32_t sb = sm0 + (i & 1) * STAGE_B;
        const uint32_t aBase = sb + (wm * 64 + a_row) * 128;
        const uint32_t bBase = sb + OFF_BH + (wn * 64 + b_row) * 128;

#pragma unroll
        for (int ks = 0; ks < 4; ks++) {
            const int cb = ks * 2;
#pragma unroll
            for (int mt = 0; mt < 4; mt++) {
                uint32_t ad = aBase + mt * 2048 + (((cb + a_c) ^ lr) << 4);
                ldsm_x4(ah[mt], ad);
                ldsm_x4(al[mt], ad + A_T_B);
            }
#pragma unroll
            for (int nt2 = 0; nt2 < 4; nt2++) {
                uint32_t bd = bBase + nt2 * 2048 + (((cb + b_c) ^ lr) << 4);
                ldsm_x4(bh[nt2], bd);
                ldsm_x4(bl[nt2], bd + B_T_B);
            }
#pragma unroll
            for (int mt = 0; mt < 4; mt++) {
#pragma unroll
                for (int nt = 0; nt < 8; nt++) {
                    const uint32_t* bhf = &bh[nt >> 1][(nt & 1) * 2];
                    const uint32_t* blf = &bl[nt >> 1][(nt & 1) * 2];
                    mma_16816(acc[mt][nt], ah[mt], bhf);
                    mma_16816(acc[mt][nt], ah[mt], blf);
                    mma_16816(acc[mt][nt], al[mt], bhf);
                }
            }
        }
    }

    // Epilogue. acc map: d0,d1 = (row qr, cols 2qc,2qc+1); d2,d3 = row qr+8
    const int qr = lane >> 2;
    const int qc = lane & 3;
#pragma unroll
    for (int mt = 0; mt < 4; mt++) {
        const size_t m0 = (size_t)by * 256 + wm * 64 + mt * 16 + qr;
#pragma unroll
        for (int nt = 0; nt < 8; nt++) {
            const size_t n0 = (size_t)bx * 128 + wn * 64 + nt * 8 + qc * 2;
            const float* d = acc[mt][nt];
            if (GELU) {
                float g0 = gelu_tanh(d[0]);
                float g1 = gelu_tanh(d[1]);
                float g2 = gelu_tanh(d[2]);
                float g3 = gelu_tanh(d[3]);
                __half h0 = __float2half_rn(g0), h1 = __float2half_rn(g1);
                __half h2 = __float2half_rn(g2), h3 = __float2half_rn(g3);
                __half l0 = __float2half_rn(g0 - __half2float(h0));
                __half l1 = __float2half_rn(g1 - __half2float(h1));
                __half l2 = __float2half_rn(g2 - __half2float(h2));
                __half l3 = __float2half_rn(g3 - __half2float(h3));
                *reinterpret_cast<__half2*>(Ch + m0 * N + n0)       = __halves2half2(h0, h1);
                *reinterpret_cast<__half2*>(Ch + (m0 + 8) * N + n0) = __halves2half2(h2, h3);
                *reinterpret_cast<__half2*>(Cl + m0 * N + n0)       = __halves2half2(l0, l1);
                *reinterpret_cast<__half2*>(Cl + (m0 + 8) * N + n0) = __halves2half2(l2, l3);
            } else {
                float2 v0; v0.x = d[0]; v0.y = d[1];
                float2 v1; v1.x = d[2]; v1.y = d[3];
                *reinterpret_cast<float2*>(Cf + m0 * N + n0)       = v0;
                *reinterpret_cast<float2*>(Cf + (m0 + 8) * N + n0) = v1;
            }
        }
    }
}

// ---------------------------------------------------------------------------
// Router: logits = x @ router_w (K=2048, E=8), softmax, fp16 round-trip
// ---------------------------------------------------------------------------
__global__ __launch_bounds__(256) void router_kernel(const float* __restrict__ x,
                                                     const float* __restrict__ rw,
                                                     float* __restrict__ probs)
{
    int n = blockIdx.x;
    int tid = threadIdx.x;
    float acc[EEXP] = {0.f, 0.f, 0.f, 0.f, 0.f, 0.f, 0.f, 0.f};
    const float* xr = x + (size_t)n * HDIM;
    for (int k = tid; k < HDIM; k += 256) {
        float xv = xr[k];
        const float4* r4 = reinterpret_cast<const float4*>(rw + (size_t)k * EEXP);
        float4 a = r4[0];
        float4 b = r4[1];
        acc[0] = fmaf(xv, a.x, acc[0]); acc[1] = fmaf(xv, a.y, acc[1]);
        acc[2] = fmaf(xv, a.z, acc[2]); acc[3] = fmaf(xv, a.w, acc[3]);
        acc[4] = fmaf(xv, b.x, acc[4]); acc[5] = fmaf(xv, b.y, acc[5]);
        acc[6] = fmaf(xv, b.z, acc[6]); acc[7] = fmaf(xv, b.w, acc[7]);
    }
    __shared__ float sbuf[EEXP][256];
#pragma unroll
    for (int e = 0; e < EEXP; e++) sbuf[e][tid] = acc[e];
    __syncthreads();
    for (int s = 128; s > 0; s >>= 1) {
        if (tid < s) {
#pragma unroll
            for (int e = 0; e < EEXP; e++) sbuf[e][tid] += sbuf[e][tid + s];
        }
        __syncthreads();
    }
    if (tid == 0) {
        float l[EEXP];
        float mmax = -1e30f;
#pragma unroll
        for (int e = 0; e < EEXP; e++) { l[e] = sbuf[e][0]; mmax = fmaxf(mmax, l[e]); }
        float s = 0.f;
#pragma unroll
        for (int e = 0; e < EEXP; e++) { l[e] = expf(l[e] - mmax); s += l[e]; }
        float inv = 1.0f / s;
#pragma unroll
        for (int e = 0; e < EEXP; e++)
            probs[n * EEXP + e] = __half2float(__float2half(l[e] * inv));
    }
}

// ---------------------------------------------------------------------------
// MoE: out[n,h] += sum_e probs[n,e] * (cb[nibble]*std + mean)
// ---------------------------------------------------------------------------
__global__ __launch_bounds__(256) void moe_kernel(const int* __restrict__ nf4,
                                                  const float* __restrict__ mean,
                                                  const float* __restrict__ stdv,
                                                  const float* __restrict__ cbg,
                                                  const float* __restrict__ probs,
                                                  float* __restrict__ out)
{
    __shared__ float cb[16];
    __shared__ float pr[EEXP];
    const int tid = threadIdx.x;
    const int n = blockIdx.x;
    if (tid < 16) cb[tid] = cbg[tid];
    if (tid < EEXP) pr[tid] = probs[n * EEXP + tid];
    __syncthreads();

    const int h0 = tid * 8;
    const int b = h0 >> 9;
    float acc[8] = {0.f, 0.f, 0.f, 0.f, 0.f, 0.f, 0.f, 0.f};

    const int4* base = reinterpret_cast<const int4*>(nf4 + (size_t)n * EEXP * (HDIM / 2)) + tid;
#pragma unroll
    for (int e = 0; e < EEXP; e++) {
        float p = pr[e];
        float sc = p * stdv[((size_t)n * EEXP + e) * 4 + b];
        float bi = p * mean[((size_t)n * EEXP + e) * 4 + b];
        int4 v = base[e * (HDIM / 2 / 4)];
        int vs[4] = {v.x, v.y, v.z, v.w};
#pragma unroll
        for (int j = 0; j < 4; j++) {
            acc[2 * j]     += fmaf(cb[vs[j] & 15], sc, bi);
            acc[2 * j + 1] += fmaf(cb[(vs[j] >> 4) & 15], sc, bi);
        }
    }

    float4* o = reinterpret_cast<float4*>(out + (size_t)n * HDIM + h0);
    float4 o0 = o[0], o1 = o[1];
    o0.x += acc[0]; o0.y += acc[1]; o0.z += acc[2]; o0.w += acc[3];
    o1.x += acc[4]; o1.y += acc[5]; o1.z += acc[6]; o1.w += acc[7];
    o[0] = o0; o[1] = o1;
}

// ---------------------------------------------------------------------------
// Launch. inputs: 0:x 1:router_w 2:nf4 3:mean 4:std 5:codebook 6:w1 7:w2
// ---------------------------------------------------------------------------
extern "C" void kernel_launch(void* const* d_in, const int* in_sizes, int n_in,
                              void* d_out, int out_size)
{
    const float* x        = (const float*)d_in[0];
    const float* router_w = (const float*)d_in[1];
    const int*   nf4      = (const int*)d_in[2];
    const float* mean     = (const float*)d_in[3];
    const float* stdv     = (const float*)d_in[4];
    const float* codebook = (const float*)d_in[5];
    const float* w1       = (const float*)d_in[6];
    const float* w2       = (const float*)d_in[7];
    float* out = (float*)d_out;

    __half *xh, *xl, *w1h, *w1l, *w2h, *w2l, *h1h, *h1l;
    float* probs;
    cudaGetSymbolAddress((void**)&xh,  g_xh);
    cudaGetSymbolAddress((void**)&xl,  g_xl);
    cudaGetSymbolAddress((void**)&w1h, g_w1h);
    cudaGetSymbolAddress((void**)&w1l, g_w1l);
    cudaGetSymbolAddress((void**)&w2h, g_w2h);
    cudaGetSymbolAddress((void**)&w2l, g_w2l);
    cudaGetSymbolAddress((void**)&h1h, g_h1h);
    cudaGetSymbolAddress((void**)&h1l, g_h1l);
    cudaGetSymbolAddress((void**)&probs, g_probs);

    const int smem_bytes = 2 * STAGE_B;   // 192 KB
    cudaFuncSetAttribute(hgemm_kernel<true>,  cudaFuncAttributeMaxDynamicSharedMemorySize, smem_bytes);
    cudaFuncSetAttribute(hgemm_kernel<false>, cudaFuncAttributeMaxDynamicSharedMemorySize, smem_bytes);

    // conversions
    split_kernel<<<(NTOK * HDIM) / 256, 256>>>(x, xh, xl, NTOK * HDIM);
    transpose_split_kernel<<<dim3(DFF / 32, HDIM / 32), 256>>>(w1, w1h, w1l, HDIM, DFF);
    transpose_split_kernel<<<dim3(HDIM / 32, DFF / 32), 256>>>(w2, w2h, w2l, DFF, HDIM);

    // router (independent)
    router_kernel<<<NTOK, 256>>>(x, router_w, probs);

    // h1 = gelu(x @ w1) -> fp16 hi/lo   [4096 x 8192]  (16 M-tiles x 64 N-tiles)
    hgemm_kernel<true><<<(NTOK / 256) * (DFF / 128), 256, smem_bytes>>>(
        xh, xl, w1h, w1l, h1h, h1l, nullptr, DFF, HDIM);

    // out = h1 @ w2                     [4096 x 2048]  (16 x 16 tiles)
    hgemm_kernel<false><<<(NTOK / 256) * (HDIM / 128), 256, smem_bytes>>>(
        h1h, h1l, w2h, w2l, nullptr, nullptr, out, HDIM, DFF);

    // out += weighted NF4 expert mix
    moe_kernel<<<NTOK, 256>>>(nf4, mean, stdv, codebook, probs, out);
}

// round 8
// speedup vs baseline: 4.7393x; 1.3858x over previous
#include <cuda_runtime.h>
#include <cuda_fp16.h>
#include <cstdint>
#include <cstddef>

// Problem constants
#define NTOK 4096   // B*L
#define HDIM 2048
#define EEXP 8
#define DFF  8192

// ---------------------------------------------------------------------------
// Scratch (device globals; no runtime allocation allowed)
// ---------------------------------------------------------------------------
__device__ __align__(256) __half g_xh[(size_t)NTOK * HDIM];
__device__ __align__(256) __half g_xl[(size_t)NTOK * HDIM];
__device__ __align__(256) __half g_w1h[(size_t)DFF * HDIM];   // transposed [DFF, HDIM]
__device__ __align__(256) __half g_w2h[(size_t)HDIM * DFF];   // transposed [HDIM, DFF]
__device__ __align__(256) __half g_h1h[(size_t)NTOK * DFF];
__device__ __align__(256) __half g_h1l[(size_t)NTOK * DFF];
__device__ __align__(256) float g_probs[NTOK * EEXP];

// ---------------------------------------------------------------------------
// PTX helpers (family-agnostic sm_80+ ops; tcgen05 unavailable on this toolchain)
// ---------------------------------------------------------------------------
__device__ __forceinline__ uint32_t smem_u32(const void* p) {
    uint32_t a;
    asm("{ .reg .u64 t; cvta.to.shared.u64 t, %1; cvt.u32.u64 %0, t; }" : "=r"(a) : "l"(p));
    return a;
}
__device__ __forceinline__ void cp_async16(uint32_t dst, const void* src) {
    asm volatile("cp.async.cg.shared.global [%0], [%1], 16;" :: "r"(dst), "l"(src));
}
__device__ __forceinline__ void cp_commit() {
    asm volatile("cp.async.commit_group;" ::: "memory");
}
template <int N>
__device__ __forceinline__ void cp_wait() {
    asm volatile("cp.async.wait_group %0;" :: "n"(N) : "memory");
}
__device__ __forceinline__ void ldsm_x4(uint32_t* r, uint32_t addr) {
    asm volatile("ldmatrix.sync.aligned.m8n8.x4.shared.b16 {%0,%1,%2,%3}, [%4];"
                 : "=r"(r[0]), "=r"(r[1]), "=r"(r[2]), "=r"(r[3]) : "r"(addr));
}
__device__ __forceinline__ void mma_16816(float* d, const uint32_t* a, const uint32_t* b) {
    asm volatile("mma.sync.aligned.m16n8k16.row.col.f32.f16.f16.f32 "
                 "{%0,%1,%2,%3}, {%4,%5,%6,%7}, {%8,%9}, {%0,%1,%2,%3};"
                 : "+f"(d[0]), "+f"(d[1]), "+f"(d[2]), "+f"(d[3])
                 : "r"(a[0]), "r"(a[1]), "r"(a[2]), "r"(a[3]), "r"(b[0]), "r"(b[1]));
}

// ---------------------------------------------------------------------------
// Conversion kernels
// ---------------------------------------------------------------------------
__global__ __launch_bounds__(256) void split_kernel(const float* __restrict__ in,
                                                    __half* __restrict__ oh,
                                                    __half* __restrict__ ol,
                                                    int n)
{
    int i = blockIdx.x * 256 + threadIdx.x;
    if (i < n) {
        float v = in[i];
        __half h = __float2half_rn(v);
        oh[i] = h;
        ol[i] = __float2half_rn(v - __half2float(h));
    }
}

// w [K,N] fp32 row-major -> oh [N,K] fp16 (transposed, K-major, hi only)
__global__ __launch_bounds__(256) void transpose_half_kernel(const float* __restrict__ w,
                                                             __half* __restrict__ oh,
                                                             int K, int N)
{
    __shared__ float t[32][33];
    const int n0 = blockIdx.x * 32;
    const int k0 = blockIdx.y * 32;
    const int tx = threadIdx.x & 31;
    const int ty = threadIdx.x >> 5;   // 0..7
#pragma unroll
    for (int r = 0; r < 4; r++) {
        int kk = ty + r * 8;
        t[kk][tx] = w[(size_t)(k0 + kk) * N + n0 + tx];
    }
    __syncthreads();
#pragma unroll
    for (int r = 0; r < 4; r++) {
        int nn = ty + r * 8;
        float v = t[tx][nn];  // = w[k0+tx][n0+nn]
        oh[(size_t)(n0 + nn) * K + k0 + tx] = __float2half_rn(v);
    }
}

// ---------------------------------------------------------------------------
// HGEMM via mma.sync: C[M,N] = op(A @ B^T)
// A [M,K] fp16 hi/lo (2-term split), B [N,K] plain fp16.
// 2 products per k-step: A_hi*B + A_lo*B (fp32 acc). Equivalent to fp32 A x
// fp16-rounded B: rel err ~2^-12 RMS — fits the 1e-3 gate with margin.
// CTA tile 256x128, BK=64, 2-stage cp.async (80 KB/stage), 8 warps 4(M)x2(N),
// warp tile 64x64. GROUP_N raster for L2 reuse.
// GELU=true: tanh-GELU then fp16 hi/lo re-split into Ch/Cl. Else fp32 Cf.
// ---------------------------------------------------------------------------
#define A_T_B   32768             // A tile bytes per term: 256 rows x 128 B
#define B_T_B   16384             // B tile bytes: 128 rows x 128 B
#define STAGE_B (2 * A_T_B + B_T_B)   // 80 KB
#define OFF_AL  A_T_B
#define OFF_BH  (2 * A_T_B)
#define GROUP_N 16

__device__ __forceinline__ float gelu_tanh(float v)
{
    float inner = 0.7978845608028654f * (v + 0.044715f * v * v * v);
    return 0.5f * v * (1.0f + tanhf(inner));
}

template <bool GELU>
__global__ __launch_bounds__(256, 1) void hgemm_kernel(const __half* __restrict__ Ah,
                                                       const __half* __restrict__ Al,
                                                       const __half* __restrict__ Bh,
                                                       __half* __restrict__ Ch,
                                                       __half* __restrict__ Cl,
                                                       float* __restrict__ Cf,
                                                       int N, int K)
{
    extern __shared__ __align__(1024) char smem[];
    const uint32_t sm0 = smem_u32(smem);

    const int tid = threadIdx.x;
    const int lane = tid & 31;
    const int wid = tid >> 5;
    const int wm = wid & 3;        // M warp coord (4) -> 64 rows each
    const int wn = wid >> 2;       // N warp coord (2) -> 64 cols each
    const int NK = K >> 6;         // K / 64

    // raster swizzle: consecutive CTAs walk M within a GROUP_N-wide N band
    const int tilesM = NTOK / 256;
    const int per_group = GROUP_N * tilesM;
    const int grp = blockIdx.x / per_group;
    const int rem = blockIdx.x % per_group;
    const int bx = grp * GROUP_N + (rem % GROUP_N);
    const int by = rem / GROUP_N;

    // ldmatrix lane decomposition
    const int g = lane >> 3;
    const int lr = lane & 7;
    const int a_row = ((g & 1) << 3) + lr;
    const int a_c = g >> 1;
    const int b_row = ((g >> 1) << 3) + lr;
    const int b_c = g & 1;

    // global load coords: thread t loads rows ld_r+32*it, 16B chunk ld_c
    const int ld_r = tid >> 3;     // 0..31
    const int ld_c = tid & 7;      // 16B chunk in 128B row
    const __half* gA[2] = {
        Ah + (size_t)(by * 256 + ld_r) * K + ld_c * 8,
        Al + (size_t)(by * 256 + ld_r) * K + ld_c * 8 };
    const __half* gBh = Bh + (size_t)(bx * 128 + ld_r) * K + ld_c * 8;

    auto load_stage = [&](int j, int slot) {
        uint32_t sb = sm0 + slot * STAGE_B;
        size_t ko = (size_t)j * 64;   // halves
#pragma unroll
        for (int t = 0; t < 2; t++) {
            const __half* src = gA[t] + ko;
            uint32_t db = sb + t * A_T_B;
#pragma unroll
            for (int it = 0; it < 8; it++) {          // 256 rows / 32
                int row = ld_r + it * 32;
                uint32_t d = db + row * 128 + ((ld_c ^ (row & 7)) << 4);
                cp_async16(d, src + (size_t)it * 32 * K);
            }
        }
        {
            const __half* src = gBh + ko;
            uint32_t db = sb + OFF_BH;
#pragma unroll
            for (int it = 0; it < 4; it++) {          // 128 rows / 32
                int row = ld_r + it * 32;
                uint32_t d = db + row * 128 + ((ld_c ^ (row & 7)) << 4);
                cp_async16(d, src + (size_t)it * 32 * K);
            }
        }
    };

    float acc[4][8][4];
#pragma unroll
    for (int mt = 0; mt < 4; mt++)
#pragma unroll
        for (int nt = 0; nt < 8; nt++)
#pragma unroll
            for (int q = 0; q < 4; q++) acc[mt][nt][q] = 0.f;

    load_stage(0, 0);
    cp_commit();

    uint32_t ah[4][4], al[4][4], bh[4][4];

    for (int i = 0; i < NK; i++) {
        cp_wait<0>();                 // chunk i resident
        __syncthreads();              // readers of slot (i+1)&1 (chunk i-1) done

        if (i + 1 < NK) {             // prefetch next chunk, overlapped w/ compute
            load_stage(i + 1, (i + 1) & 1);
            cp_commit();
        }

        const uint32_t sb = sm0 + (i & 1) * STAGE_B;
        const uint32_t aBase = sb + (wm * 64 + a_row) * 128;
        const uint32_t bBase = sb + OFF_BH + (wn * 64 + b_row) * 128;

#pragma unroll
        for (int ks = 0; ks < 4; ks++) {
            const int cb = ks * 2;
#pragma unroll
            for (int mt = 0; mt < 4; mt++) {
                uint32_t ad = aBase + mt * 2048 + (((cb + a_c) ^ lr) << 4);
                ldsm_x4(ah[mt], ad);
                ldsm_x4(al[mt], ad + A_T_B);
            }
#pragma unroll
            for (int nt2 = 0; nt2 < 4; nt2++) {
                uint32_t bd = bBase + nt2 * 2048 + (((cb + b_c) ^ lr) << 4);
                ldsm_x4(bh[nt2], bd);
            }
#pragma unroll
            for (int mt = 0; mt < 4; mt++) {
#pragma unroll
                for (int nt = 0; nt < 8; nt++) {
                    const uint32_t* bhf = &bh[nt >> 1][(nt & 1) * 2];
                    mma_16816(acc[mt][nt], ah[mt], bhf);
                    mma_16816(acc[mt][nt], al[mt], bhf);
                }
            }
        }
    }

    // Epilogue. acc map: d0,d1 = (row qr, cols 2qc,2qc+1); d2,d3 = row qr+8
    const int qr = lane >> 2;
    const int qc = lane & 3;
#pragma unroll
    for (int mt = 0; mt < 4; mt++) {
        const size_t m0 = (size_t)by * 256 + wm * 64 + mt * 16 + qr;
#pragma unroll
        for (int nt = 0; nt < 8; nt++) {
            const size_t n0 = (size_t)bx * 128 + wn * 64 + nt * 8 + qc * 2;
            const float* d = acc[mt][nt];
            if (GELU) {
                float g0 = gelu_tanh(d[0]);
                float g1 = gelu_tanh(d[1]);
                float g2 = gelu_tanh(d[2]);
                float g3 = gelu_tanh(d[3]);
                __half h0 = __float2half_rn(g0), h1 = __float2half_rn(g1);
                __half h2 = __float2half_rn(g2), h3 = __float2half_rn(g3);
                __half l0 = __float2half_rn(g0 - __half2float(h0));
                __half l1 = __float2half_rn(g1 - __half2float(h1));
                __half l2 = __float2half_rn(g2 - __half2float(h2));
                __half l3 = __float2half_rn(g3 - __half2float(h3));
                *reinterpret_cast<__half2*>(Ch + m0 * N + n0)       = __halves2half2(h0, h1);
                *reinterpret_cast<__half2*>(Ch + (m0 + 8) * N + n0) = __halves2half2(h2, h3);
                *reinterpret_cast<__half2*>(Cl + m0 * N + n0)       = __halves2half2(l0, l1);
                *reinterpret_cast<__half2*>(Cl + (m0 + 8) * N + n0) = __halves2half2(l2, l3);
            } else {
                float2 v0; v0.x = d[0]; v0.y = d[1];
                float2 v1; v1.x = d[2]; v1.y = d[3];
                *reinterpret_cast<float2*>(Cf + m0 * N + n0)       = v0;
                *reinterpret_cast<float2*>(Cf + (m0 + 8) * N + n0) = v1;
            }
        }
    }
}

// ---------------------------------------------------------------------------
// Router: logits = x @ router_w (K=2048, E=8), softmax, fp16 round-trip
// ---------------------------------------------------------------------------
__global__ __launch_bounds__(256) void router_kernel(const float* __restrict__ x,
                                                     const float* __restrict__ rw,
                                                     float* __restrict__ probs)
{
    int n = blockIdx.x;
    int tid = threadIdx.x;
    float acc[EEXP] = {0.f, 0.f, 0.f, 0.f, 0.f, 0.f, 0.f, 0.f};
    const float* xr = x + (size_t)n * HDIM;
    for (int k = tid; k < HDIM; k += 256) {
        float xv = xr[k];
        const float4* r4 = reinterpret_cast<const float4*>(rw + (size_t)k * EEXP);
        float4 a = r4[0];
        float4 b = r4[1];
        acc[0] = fmaf(xv, a.x, acc[0]); acc[1] = fmaf(xv, a.y, acc[1]);
        acc[2] = fmaf(xv, a.z, acc[2]); acc[3] = fmaf(xv, a.w, acc[3]);
        acc[4] = fmaf(xv, b.x, acc[4]); acc[5] = fmaf(xv, b.y, acc[5]);
        acc[6] = fmaf(xv, b.z, acc[6]); acc[7] = fmaf(xv, b.w, acc[7]);
    }
    __shared__ float sbuf[EEXP][256];
#pragma unroll
    for (int e = 0; e < EEXP; e++) sbuf[e][tid] = acc[e];
    __syncthreads();
    for (int s = 128; s > 0; s >>= 1) {
        if (tid < s) {
#pragma unroll
            for (int e = 0; e < EEXP; e++) sbuf[e][tid] += sbuf[e][tid + s];
        }
        __syncthreads();
    }
    if (tid == 0) {
        float l[EEXP];
        float mmax = -1e30f;
#pragma unroll
        for (int e = 0; e < EEXP; e++) { l[e] = sbuf[e][0]; mmax = fmaxf(mmax, l[e]); }
        float s = 0.f;
#pragma unroll
        for (int e = 0; e < EEXP; e++) { l[e] = expf(l[e] - mmax); s += l[e]; }
        float inv = 1.0f / s;
#pragma unroll
        for (int e = 0; e < EEXP; e++)
            probs[n * EEXP + e] = __half2float(__float2half(l[e] * inv));
    }
}

// ---------------------------------------------------------------------------
// MoE: out[n,h] += sum_e probs[n,e] * (cb[nibble]*std + mean)
// ---------------------------------------------------------------------------
__global__ __launch_bounds__(256) void moe_kernel(const int* __restrict__ nf4,
                                                  const float* __restrict__ mean,
                                                  const float* __restrict__ stdv,
                                                  const float* __restrict__ cbg,
                                                  const float* __restrict__ probs,
                                                  float* __restrict__ out)
{
    __shared__ float cb[16];
    __shared__ float pr[EEXP];
    const int tid = threadIdx.x;
    const int n = blockIdx.x;
    if (tid < 16) cb[tid] = cbg[tid];
    if (tid < EEXP) pr[tid] = probs[n * EEXP + tid];
    __syncthreads();

    const int h0 = tid * 8;
    const int b = h0 >> 9;
    float acc[8] = {0.f, 0.f, 0.f, 0.f, 0.f, 0.f, 0.f, 0.f};

    const int4* base = reinterpret_cast<const int4*>(nf4 + (size_t)n * EEXP * (HDIM / 2)) + tid;
#pragma unroll
    for (int e = 0; e < EEXP; e++) {
        float p = pr[e];
        float sc = p * stdv[((size_t)n * EEXP + e) * 4 + b];
        float bi = p * mean[((size_t)n * EEXP + e) * 4 + b];
        int4 v = base[e * (HDIM / 2 / 4)];
        int vs[4] = {v.x, v.y, v.z, v.w};
#pragma unroll
        for (int j = 0; j < 4; j++) {
            acc[2 * j]     += fmaf(cb[vs[j] & 15], sc, bi);
            acc[2 * j + 1] += fmaf(cb[(vs[j] >> 4) & 15], sc, bi);
        }
    }

    float4* o = reinterpret_cast<float4*>(out + (size_t)n * HDIM + h0);
    float4 o0 = o[0], o1 = o[1];
    o0.x += acc[0]; o0.y += acc[1]; o0.z += acc[2]; o0.w += acc[3];
    o1.x += acc[4]; o1.y += acc[5]; o1.z += acc[6]; o1.w += acc[7];
    o[0] = o0; o[1] = o1;
}

// ---------------------------------------------------------------------------
// Launch. inputs: 0:x 1:router_w 2:nf4 3:mean 4:std 5:codebook 6:w1 7:w2
// ---------------------------------------------------------------------------
extern "C" void kernel_launch(void* const* d_in, const int* in_sizes, int n_in,
                              void* d_out, int out_size)
{
    const float* x        = (const float*)d_in[0];
    const float* router_w = (const float*)d_in[1];
    const int*   nf4      = (const int*)d_in[2];
    const float* mean     = (const float*)d_in[3];
    const float* stdv     = (const float*)d_in[4];
    const float* codebook = (const float*)d_in[5];
    const float* w1       = (const float*)d_in[6];
    const float* w2       = (const float*)d_in[7];
    float* out = (float*)d_out;

    __half *xh, *xl, *w1h, *w2h, *h1h, *h1l;
    float* probs;
    cudaGetSymbolAddress((void**)&xh,  g_xh);
    cudaGetSymbolAddress((void**)&xl,  g_xl);
    cudaGetSymbolAddress((void**)&w1h, g_w1h);
    cudaGetSymbolAddress((void**)&w2h, g_w2h);
    cudaGetSymbolAddress((void**)&h1h, g_h1h);
    cudaGetSymbolAddress((void**)&h1l, g_h1l);
    cudaGetSymbolAddress((void**)&probs, g_probs);

    const int smem_bytes = 2 * STAGE_B;   // 160 KB
    cudaFuncSetAttribute(hgemm_kernel<true>,  cudaFuncAttributeMaxDynamicSharedMemorySize, smem_bytes);
    cudaFuncSetAttribute(hgemm_kernel<false>, cudaFuncAttributeMaxDynamicSharedMemorySize, smem_bytes);

    // conversions (w: hi only)
    split_kernel<<<(NTOK * HDIM) / 256, 256>>>(x, xh, xl, NTOK * HDIM);
    transpose_half_kernel<<<dim3(DFF / 32, HDIM / 32), 256>>>(w1, w1h, HDIM, DFF);
    transpose_half_kernel<<<dim3(HDIM / 32, DFF / 32), 256>>>(w2, w2h, DFF, HDIM);

    // router (independent)
    router_kernel<<<NTOK, 256>>>(x, router_w, probs);

    // h1 = gelu(x @ w1) -> fp16 hi/lo   [4096 x 8192]
    hgemm_kernel<true><<<(NTOK / 256) * (DFF / 128), 256, smem_bytes>>>(
        xh, xl, w1h, h1h, h1l, nullptr, DFF, HDIM);

    // out = h1 @ w2                     [4096 x 2048]
    hgemm_kernel<false><<<(NTOK / 256) * (HDIM / 128), 256, smem_bytes>>>(
        h1h, h1l, w2h, nullptr, nullptr, out, HDIM, DFF);

    // out += weighted NF4 expert mix
    moe_kernel<<<NTOK, 256>>>(nf4, mean, stdv, codebook, probs, out);
}

// round 9
// speedup vs baseline: 7.9907x; 1.6860x over previous
#include <cuda_runtime.h>
#include <cuda_fp16.h>
#include <cstdint>
#include <cstddef>

// Problem constants
#define NTOK 4096   // B*L
#define HDIM 2048
#define EEXP 8
#define DFF  8192

// ---------------------------------------------------------------------------
// Scratch (device globals; no runtime allocation allowed)
// ---------------------------------------------------------------------------
__device__ __align__(256) __half g_xh[(size_t)NTOK * HDIM];
__device__ __align__(256) __half g_w1h[(size_t)DFF * HDIM];   // transposed [DFF, HDIM]
__device__ __align__(256) __half g_w2h[(size_t)HDIM * DFF];   // transposed [HDIM, DFF]
__device__ __align__(256) __half g_h1h[(size_t)NTOK * DFF];
__device__ __align__(256) float g_probs[NTOK * EEXP];

// ---------------------------------------------------------------------------
// PTX helpers (family-agnostic sm_80+ ops; tcgen05 unavailable on this toolchain)
// ---------------------------------------------------------------------------
__device__ __forceinline__ uint32_t smem_u32(const void* p) {
    uint32_t a;
    asm("{ .reg .u64 t; cvta.to.shared.u64 t, %1; cvt.u32.u64 %0, t; }" : "=r"(a) : "l"(p));
    return a;
}
__device__ __forceinline__ void cp_async16(uint32_t dst, const void* src) {
    asm volatile("cp.async.cg.shared.global [%0], [%1], 16;" :: "r"(dst), "l"(src));
}
__device__ __forceinline__ void cp_commit() {
    asm volatile("cp.async.commit_group;" ::: "memory");
}
template <int N>
__device__ __forceinline__ void cp_wait() {
    asm volatile("cp.async.wait_group %0;" :: "n"(N) : "memory");
}
__device__ __forceinline__ void ldsm_x4(uint32_t* r, uint32_t addr) {
    asm volatile("ldmatrix.sync.aligned.m8n8.x4.shared.b16 {%0,%1,%2,%3}, [%4];"
                 : "=r"(r[0]), "=r"(r[1]), "=r"(r[2]), "=r"(r[3]) : "r"(addr));
}
__device__ __forceinline__ void mma_16816(float* d, const uint32_t* a, const uint32_t* b) {
    asm volatile("mma.sync.aligned.m16n8k16.row.col.f32.f16.f16.f32 "
                 "{%0,%1,%2,%3}, {%4,%5,%6,%7}, {%8,%9}, {%0,%1,%2,%3};"
                 : "+f"(d[0]), "+f"(d[1]), "+f"(d[2]), "+f"(d[3])
                 : "r"(a[0]), "r"(a[1]), "r"(a[2]), "r"(a[3]), "r"(b[0]), "r"(b[1]));
}

// ---------------------------------------------------------------------------
// Conversion kernels
// ---------------------------------------------------------------------------
__global__ __launch_bounds__(256) void convert_half_kernel(const float* __restrict__ in,
                                                           __half* __restrict__ oh,
                                                           int n)
{
    int i = blockIdx.x * 256 + threadIdx.x;
    if (i < n) oh[i] = __float2half_rn(in[i]);
}

// w [K,N] fp32 row-major -> oh [N,K] fp16 (transposed, K-major)
__global__ __launch_bounds__(256) void transpose_half_kernel(const float* __restrict__ w,
                                                             __half* __restrict__ oh,
                                                             int K, int N)
{
    __shared__ float t[32][33];
    const int n0 = blockIdx.x * 32;
    const int k0 = blockIdx.y * 32;
    const int tx = threadIdx.x & 31;
    const int ty = threadIdx.x >> 5;   // 0..7
#pragma unroll
    for (int r = 0; r < 4; r++) {
        int kk = ty + r * 8;
        t[kk][tx] = w[(size_t)(k0 + kk) * N + n0 + tx];
    }
    __syncthreads();
#pragma unroll
    for (int r = 0; r < 4; r++) {
        int nn = ty + r * 8;
        oh[(size_t)(n0 + nn) * K + k0 + tx] = __float2half_rn(t[tx][nn]);
    }
}

// ---------------------------------------------------------------------------
// HGEMM via mma.sync: C[M,N] = op(A @ B^T)
// A [M,K] fp16, B [N,K] fp16, single product, fp32 accumulate.
// fp16 rounding of x/w1/w2/h1 -> end-to-end rel err ~4e-4 (< 1e-3 gate).
// CTA tile 256x128, BK=64, 2-stage cp.async (48 KB/stage), 8 warps 4(M)x2(N),
// warp tile 64x64. GROUP_N raster for L2 reuse.
// GELU=true: tanh-GELU, write fp16 Ch. Else write fp32 Cf.
// ---------------------------------------------------------------------------
#define A_T_B   32768             // A tile bytes: 256 rows x 128 B
#define B_T_B   16384             // B tile bytes: 128 rows x 128 B
#define STAGE_B (A_T_B + B_T_B)   // 48 KB
#define OFF_BH  A_T_B
#define GROUP_N 16

__device__ __forceinline__ float gelu_tanh(float v)
{
    float inner = 0.7978845608028654f * (v + 0.044715f * v * v * v);
    return 0.5f * v * (1.0f + tanhf(inner));
}

template <bool GELU>
__global__ __launch_bounds__(256, 1) void hgemm_kernel(const __half* __restrict__ Ah,
                                                       const __half* __restrict__ Bh,
                                                       __half* __restrict__ Ch,
                                                       float* __restrict__ Cf,
                                                       int N, int K)
{
    extern __shared__ __align__(1024) char smem[];
    const uint32_t sm0 = smem_u32(smem);

    const int tid = threadIdx.x;
    const int lane = tid & 31;
    const int wid = tid >> 5;
    const int wm = wid & 3;        // M warp coord (4) -> 64 rows each
    const int wn = wid >> 2;       // N warp coord (2) -> 64 cols each
    const int NK = K >> 6;         // K / 64

    // raster swizzle: consecutive CTAs walk M within a GROUP_N-wide N band
    const int tilesM = NTOK / 256;
    const int per_group = GROUP_N * tilesM;
    const int grp = blockIdx.x / per_group;
    const int rem = blockIdx.x % per_group;
    const int bx = grp * GROUP_N + (rem % GROUP_N);
    const int by = rem / GROUP_N;

    // ldmatrix lane decomposition
    const int g = lane >> 3;
    const int lr = lane & 7;
    const int a_row = ((g & 1) << 3) + lr;
    const int a_c = g >> 1;
    const int b_row = ((g >> 1) << 3) + lr;
    const int b_c = g & 1;

    // global load coords: thread t loads rows ld_r+32*it, 16B chunk ld_c
    const int ld_r = tid >> 3;     // 0..31
    const int ld_c = tid & 7;      // 16B chunk in 128B row
    const __half* gA = Ah + (size_t)(by * 256 + ld_r) * K + ld_c * 8;
    const __half* gB = Bh + (size_t)(bx * 128 + ld_r) * K + ld_c * 8;

    auto load_stage = [&](int j, int slot) {
        uint32_t sb = sm0 + slot * STAGE_B;
        size_t ko = (size_t)j * 64;   // halves
        {
            const __half* src = gA + ko;
#pragma unroll
            for (int it = 0; it < 8; it++) {          // 256 rows / 32
                int row = ld_r + it * 32;
                uint32_t d = sb + row * 128 + ((ld_c ^ (row & 7)) << 4);
                cp_async16(d, src + (size_t)it * 32 * K);
            }
        }
        {
            const __half* src = gB + ko;
            uint32_t db = sb + OFF_BH;
#pragma unroll
            for (int it = 0; it < 4; it++) {          // 128 rows / 32
                int row = ld_r + it * 32;
                uint32_t d = db + row * 128 + ((ld_c ^ (row & 7)) << 4);
                cp_async16(d, src + (size_t)it * 32 * K);
            }
        }
    };

    float acc[4][8][4];
#pragma unroll
    for (int mt = 0; mt < 4; mt++)
#pragma unroll
        for (int nt = 0; nt < 8; nt++)
#pragma unroll
            for (int q = 0; q < 4; q++) acc[mt][nt][q] = 0.f;

    load_stage(0, 0);
    cp_commit();

    uint32_t ah[4][4], bh[4][4];

    for (int i = 0; i < NK; i++) {
        cp_wait<0>();                 // chunk i resident
        __syncthreads();              // readers of slot (i+1)&1 (chunk i-1) done

        if (i + 1 < NK) {             // prefetch next chunk, overlapped w/ compute
            load_stage(i + 1, (i + 1) & 1);
            cp_commit();
        }

        const uint32_t sb = sm0 + (i & 1) * STAGE_B;
        const uint32_t aBase = sb + (wm * 64 + a_row) * 128;
        const uint32_t bBase = sb + OFF_BH + (wn * 64 + b_row) * 128;

#pragma unroll
        for (int ks = 0; ks < 4; ks++) {
            const int cb = ks * 2;
#pragma unroll
            for (int mt = 0; mt < 4; mt++) {
                uint32_t ad = aBase + mt * 2048 + (((cb + a_c) ^ lr) << 4);
                ldsm_x4(ah[mt], ad);
            }
#pragma unroll
            for (int nt2 = 0; nt2 < 4; nt2++) {
                uint32_t bd = bBase + nt2 * 2048 + (((cb + b_c) ^ lr) << 4);
                ldsm_x4(bh[nt2], bd);
            }
#pragma unroll
            for (int mt = 0; mt < 4; mt++) {
#pragma unroll
                for (int nt = 0; nt < 8; nt++) {
                    const uint32_t* bhf = &bh[nt >> 1][(nt & 1) * 2];
                    mma_16816(acc[mt][nt], ah[mt], bhf);
                }
            }
        }
    }

    // Epilogue. acc map: d0,d1 = (row qr, cols 2qc,2qc+1); d2,d3 = row qr+8
    const int qr = lane >> 2;
    const int qc = lane & 3;
#pragma unroll
    for (int mt = 0; mt < 4; mt++) {
        const size_t m0 = (size_t)by * 256 + wm * 64 + mt * 16 + qr;
#pragma unroll
        for (int nt = 0; nt < 8; nt++) {
            const size_t n0 = (size_t)bx * 128 + wn * 64 + nt * 8 + qc * 2;
            const float* d = acc[mt][nt];
            if (GELU) {
                __half h0 = __float2half_rn(gelu_tanh(d[0]));
                __half h1 = __float2half_rn(gelu_tanh(d[1]));
                __half h2 = __float2half_rn(gelu_tanh(d[2]));
                __half h3 = __float2half_rn(gelu_tanh(d[3]));
                *reinterpret_cast<__half2*>(Ch + m0 * N + n0)       = __halves2half2(h0, h1);
                *reinterpret_cast<__half2*>(Ch + (m0 + 8) * N + n0) = __halves2half2(h2, h3);
            } else {
                float2 v0; v0.x = d[0]; v0.y = d[1];
                float2 v1; v1.x = d[2]; v1.y = d[3];
                *reinterpret_cast<float2*>(Cf + m0 * N + n0)       = v0;
                *reinterpret_cast<float2*>(Cf + (m0 + 8) * N + n0) = v1;
            }
        }
    }
}

// ---------------------------------------------------------------------------
// Router: logits = x @ router_w (K=2048, E=8), softmax, fp16 round-trip
// ---------------------------------------------------------------------------
__global__ __launch_bounds__(256) void router_kernel(const float* __restrict__ x,
                                                     const float* __restrict__ rw,
                                                     float* __restrict__ probs)
{
    int n = blockIdx.x;
    int tid = threadIdx.x;
    float acc[EEXP] = {0.f, 0.f, 0.f, 0.f, 0.f, 0.f, 0.f, 0.f};
    const float* xr = x + (size_t)n * HDIM;
    for (int k = tid; k < HDIM; k += 256) {
        float xv = xr[k];
        const float4* r4 = reinterpret_cast<const float4*>(rw + (size_t)k * EEXP);
        float4 a = r4[0];
        float4 b = r4[1];
        acc[0] = fmaf(xv, a.x, acc[0]); acc[1] = fmaf(xv, a.y, acc[1]);
        acc[2] = fmaf(xv, a.z, acc[2]); acc[3] = fmaf(xv, a.w, acc[3]);
        acc[4] = fmaf(xv, b.x, acc[4]); acc[5] = fmaf(xv, b.y, acc[5]);
        acc[6] = fmaf(xv, b.z, acc[6]); acc[7] = fmaf(xv, b.w, acc[7]);
    }
    __shared__ float sbuf[EEXP][256];
#pragma unroll
    for (int e = 0; e < EEXP; e++) sbuf[e][tid] = acc[e];
    __syncthreads();
    for (int s = 128; s > 0; s >>= 1) {
        if (tid < s) {
#pragma unroll
            for (int e = 0; e < EEXP; e++) sbuf[e][tid] += sbuf[e][tid + s];
        }
        __syncthreads();
    }
    if (tid == 0) {
        float l[EEXP];
        float mmax = -1e30f;
#pragma unroll
        for (int e = 0; e < EEXP; e++) { l[e] = sbuf[e][0]; mmax = fmaxf(mmax, l[e]); }
        float s = 0.f;
#pragma unroll
        for (int e = 0; e < EEXP; e++) { l[e] = expf(l[e] - mmax); s += l[e]; }
        float inv = 1.0f / s;
#pragma unroll
        for (int e = 0; e < EEXP; e++)
            probs[n * EEXP + e] = __half2float(__float2half(l[e] * inv));
    }
}

// ---------------------------------------------------------------------------
// MoE: out[n,h] += sum_e probs[n,e] * (cb[nibble]*std + mean)
// ---------------------------------------------------------------------------
__global__ __launch_bounds__(256) void moe_kernel(const int* __restrict__ nf4,
                                                  const float* __restrict__ mean,
                                                  const float* __restrict__ stdv,
                                                  const float* __restrict__ cbg,
                                                  const float* __restrict__ probs,
                                                  float* __restrict__ out)
{
    __shared__ float cb[16];
    __shared__ float pr[EEXP];
    const int tid = threadIdx.x;
    const int n = blockIdx.x;
    if (tid < 16) cb[tid] = cbg[tid];
    if (tid < EEXP) pr[tid] = probs[n * EEXP + tid];
    __syncthreads();

    const int h0 = tid * 8;
    const int b = h0 >> 9;
    float acc[8] = {0.f, 0.f, 0.f, 0.f, 0.f, 0.f, 0.f, 0.f};

    const int4* base = reinterpret_cast<const int4*>(nf4 + (size_t)n * EEXP * (HDIM / 2)) + tid;
#pragma unroll
    for (int e = 0; e < EEXP; e++) {
        float p = pr[e];
        float sc = p * stdv[((size_t)n * EEXP + e) * 4 + b];
        float bi = p * mean[((size_t)n * EEXP + e) * 4 + b];
        int4 v = base[e * (HDIM / 2 / 4)];
        int vs[4] = {v.x, v.y, v.z, v.w};
#pragma unroll
        for (int j = 0; j < 4; j++) {
            acc[2 * j]     += fmaf(cb[vs[j] & 15], sc, bi);
            acc[2 * j + 1] += fmaf(cb[(vs[j] >> 4) & 15], sc, bi);
        }
    }

    float4* o = reinterpret_cast<float4*>(out + (size_t)n * HDIM + h0);
    float4 o0 = o[0], o1 = o[1];
    o0.x += acc[0]; o0.y += acc[1]; o0.z += acc[2]; o0.w += acc[3];
    o1.x += acc[4]; o1.y += acc[5]; o1.z += acc[6]; o1.w += acc[7];
    o[0] = o0; o[1] = o1;
}

// ---------------------------------------------------------------------------
// Launch. inputs: 0:x 1:router_w 2:nf4 3:mean 4:std 5:codebook 6:w1 7:w2
// ---------------------------------------------------------------------------
extern "C" void kernel_launch(void* const* d_in, const int* in_sizes, int n_in,
                              void* d_out, int out_size)
{
    const float* x        = (const float*)d_in[0];
    const float* router_w = (const float*)d_in[1];
    const int*   nf4      = (const int*)d_in[2];
    const float* mean     = (const float*)d_in[3];
    const float* stdv     = (const float*)d_in[4];
    const float* codebook = (const float*)d_in[5];
    const float* w1       = (const float*)d_in[6];
    const float* w2       = (const float*)d_in[7];
    float* out = (float*)d_out;

    __half *xh, *w1h, *w2h, *h1h;
    float* probs;
    cudaGetSymbolAddress((void**)&xh,  g_xh);
    cudaGetSymbolAddress((void**)&w1h, g_w1h);
    cudaGetSymbolAddress((void**)&w2h, g_w2h);
    cudaGetSymbolAddress((void**)&h1h, g_h1h);
    cudaGetSymbolAddress((void**)&probs, g_probs);

    const int smem_bytes = 2 * STAGE_B;   // 96 KB
    cudaFuncSetAttribute(hgemm_kernel<true>,  cudaFuncAttributeMaxDynamicSharedMemorySize, smem_bytes);
    cudaFuncSetAttribute(hgemm_kernel<false>, cudaFuncAttributeMaxDynamicSharedMemorySize, smem_bytes);

    // conversions (all plain fp16)
    convert_half_kernel<<<(NTOK * HDIM) / 256, 256>>>(x, xh, NTOK * HDIM);
    transpose_half_kernel<<<dim3(DFF / 32, HDIM / 32), 256>>>(w1, w1h, HDIM, DFF);
    transpose_half_kernel<<<dim3(HDIM / 32, DFF / 32), 256>>>(w2, w2h, DFF, HDIM);

    // router (independent, reads fp32 x)
    router_kernel<<<NTOK, 256>>>(x, router_w, probs);

    // h1 = gelu(x @ w1) -> fp16   [4096 x 8192]
    hgemm_kernel<true><<<(NTOK / 256) * (DFF / 128), 256, smem_bytes>>>(
        xh, w1h, h1h, nullptr, DFF, HDIM);

    // out = h1 @ w2               [4096 x 2048]
    hgemm_kernel<false><<<(NTOK / 256) * (HDIM / 128), 256, smem_bytes>>>(
        h1h, w2h, nullptr, out, HDIM, DFF);

    // out += weighted NF4 expert mix
    moe_kernel<<<NTOK, 256>>>(nf4, mean, stdv, codebook, probs, out);
}

// round 11
// speedup vs baseline: 8.4629x; 1.0591x over previous
#include <cuda_runtime.h>
#include <cuda_fp16.h>
#include <cstdint>
#include <cstddef>

// Problem constants
#define NTOK 4096   // B*L
#define HDIM 2048
#define EEXP 8
#define DFF  8192

// ---------------------------------------------------------------------------
// Scratch (device globals; no runtime allocation allowed)
// ---------------------------------------------------------------------------
__device__ __align__(256) __half g_xh[(size_t)NTOK * HDIM];
__device__ __align__(256) __half g_w1h[(size_t)DFF * HDIM];   // transposed [DFF, HDIM]
__device__ __align__(256) __half g_w2h[(size_t)HDIM * DFF];   // transposed [HDIM, DFF]
__device__ __align__(256) __half g_h1h[(size_t)NTOK * DFF];
__device__ __align__(256) float g_probs[NTOK * EEXP];

// ---------------------------------------------------------------------------
// PTX helpers (family-agnostic sm_80+ ops; tcgen05 unavailable on this toolchain)
// ---------------------------------------------------------------------------
__device__ __forceinline__ uint32_t smem_u32(const void* p) {
    uint32_t a;
    asm("{ .reg .u64 t; cvta.to.shared.u64 t, %1; cvt.u32.u64 %0, t; }" : "=r"(a) : "l"(p));
    return a;
}
__device__ __forceinline__ void cp_async16(uint32_t dst, const void* src) {
    asm volatile("cp.async.cg.shared.global [%0], [%1], 16;" :: "r"(dst), "l"(src));
}
__device__ __forceinline__ void cp_commit() {
    asm volatile("cp.async.commit_group;" ::: "memory");
}
template <int N>
__device__ __forceinline__ void cp_wait() {
    asm volatile("cp.async.wait_group %0;" :: "n"(N) : "memory");
}
__device__ __forceinline__ void ldsm_x4(uint32_t* r, uint32_t addr) {
    asm volatile("ldmatrix.sync.aligned.m8n8.x4.shared.b16 {%0,%1,%2,%3}, [%4];"
                 : "=r"(r[0]), "=r"(r[1]), "=r"(r[2]), "=r"(r[3]) : "r"(addr));
}
__device__ __forceinline__ void mma_16816(float* d, const uint32_t* a, const uint32_t* b) {
    asm volatile("mma.sync.aligned.m16n8k16.row.col.f32.f16.f16.f32 "
                 "{%0,%1,%2,%3}, {%4,%5,%6,%7}, {%8,%9}, {%0,%1,%2,%3};"
                 : "+f"(d[0]), "+f"(d[1]), "+f"(d[2]), "+f"(d[3])
                 : "r"(a[0]), "r"(a[1]), "r"(a[2]), "r"(a[3]), "r"(b[0]), "r"(b[1]));
}

// ---------------------------------------------------------------------------
// Conversion kernel: w [K,N] fp32 row-major -> oh [N,K] fp16 (transposed)
// ---------------------------------------------------------------------------
__global__ __launch_bounds__(256) void transpose_half_kernel(const float* __restrict__ w,
                                                             __half* __restrict__ oh,
                                                             int K, int N)
{
    __shared__ float t[32][33];
    const int n0 = blockIdx.x * 32;
    const int k0 = blockIdx.y * 32;
    const int tx = threadIdx.x & 31;
    const int ty = threadIdx.x >> 5;   // 0..7
#pragma unroll
    for (int r = 0; r < 4; r++) {
        int kk = ty + r * 8;
        t[kk][tx] = w[(size_t)(k0 + kk) * N + n0 + tx];
    }
    __syncthreads();
#pragma unroll
    for (int r = 0; r < 4; r++) {
        int nn = ty + r * 8;
        oh[(size_t)(n0 + nn) * K + k0 + tx] = __float2half_rn(t[tx][nn]);
    }
}

// ---------------------------------------------------------------------------
// HGEMM via mma.sync: C[M,N] = op(A @ B^T)
// A [M,K] fp16, B [N,K] fp16, single product, fp32 accumulate.
// CTA tile 256x128, BK=128 (256B rows, 4-bit chunk XOR swizzle), 2-stage
// cp.async (96 KB/stage), 8 warps 4(M)x2(N), warp tile 64x64.
// GELU=true: tanh-GELU, write fp16 Ch. Else write fp32 Cf.
// ---------------------------------------------------------------------------
#define A_T_B   65536             // A tile: 256 rows x 256 B
#define B_T_B   32768             // B tile: 128 rows x 256 B
#define STAGE_B (A_T_B + B_T_B)   // 96 KB
#define OFF_BH  A_T_B
#define GROUP_N 16

__device__ __forceinline__ float gelu_tanh(float v)
{
    float inner = 0.7978845608028654f * (v + 0.044715f * v * v * v);
    return 0.5f * v * (1.0f + tanhf(inner));
}

template <bool GELU>
__global__ __launch_bounds__(256, 1) void hgemm_kernel(const __half* __restrict__ Ah,
                                                       const __half* __restrict__ Bh,
                                                       __half* __restrict__ Ch,
                                                       float* __restrict__ Cf,
                                                       int N, int K)
{
    extern __shared__ __align__(1024) char smem[];
    const uint32_t sm0 = smem_u32(smem);

    const int tid = threadIdx.x;
    const int lane = tid & 31;
    const int wid = tid >> 5;
    const int wm = wid & 3;        // M warp coord (4) -> 64 rows each
    const int wn = wid >> 2;       // N warp coord (2) -> 64 cols each
    const int NK = K >> 7;         // K / 128

    // raster swizzle: consecutive CTAs walk M within a GROUP_N-wide N band
    const int tilesM = NTOK / 256;
    const int per_group = GROUP_N * tilesM;
    const int grp = blockIdx.x / per_group;
    const int rem = blockIdx.x % per_group;
    const int bx = grp * GROUP_N + (rem % GROUP_N);
    const int by = rem / GROUP_N;

    // ldmatrix lane decomposition
    const int g = lane >> 3;
    const int lr = lane & 7;
    const int a_row = ((g & 1) << 3) + lr;
    const int a_c = g >> 1;
    const int b_row = ((g >> 1) << 3) + lr;
    const int b_c = g & 1;

    // global load coords
    const int ld_r = tid >> 3;     // 0..31
    const int ld_c = tid & 7;      // base 16B chunk (of 16 per 256B row)
    const __half* gA = Ah + (size_t)(by * 256 + ld_r) * K;
    const __half* gB = Bh + (size_t)(bx * 128 + ld_r) * K;

    auto load_stage = [&](int j, int slot) {
        uint32_t sb = sm0 + slot * STAGE_B;
        size_t ko = (size_t)j * 128;   // halves
        // A: 256 rows x 16 chunks
#pragma unroll
        for (int it = 0; it < 8; it++) {
            int row = ld_r + it * 32;
            const __half* src = gA + ko + (size_t)it * 32 * K;
            uint32_t rb = sb + row * 256;
#pragma unroll
            for (int h = 0; h < 2; h++) {
                int c = ld_c + h * 8;
                cp_async16(rb + ((c ^ (row & 7)) << 4), src + c * 8);
            }
        }
        // B: 128 rows x 16 chunks
#pragma unroll
        for (int it = 0; it < 4; it++) {
            int row = ld_r + it * 32;
            const __half* src = gB + ko + (size_t)it * 32 * K;
            uint32_t rb = sb + OFF_BH + row * 256;
#pragma unroll
            for (int h = 0; h < 2; h++) {
                int c = ld_c + h * 8;
                cp_async16(rb + ((c ^ (row & 7)) << 4), src + c * 8);
            }
        }
    };

    float acc[4][8][4];
#pragma unroll
    for (int mt = 0; mt < 4; mt++)
#pragma unroll
        for (int nt = 0; nt < 8; nt++)
#pragma unroll
            for (int q = 0; q < 4; q++) acc[mt][nt][q] = 0.f;

    load_stage(0, 0);
    cp_commit();

    uint32_t ah[4][4], bh[4][4];

    for (int i = 0; i < NK; i++) {
        cp_wait<0>();                 // chunk i resident
        __syncthreads();              // readers of the other slot done

        if (i + 1 < NK) {             // prefetch next chunk, overlapped w/ compute
            load_stage(i + 1, (i + 1) & 1);
            cp_commit();
        }

        const uint32_t sb = sm0 + (i & 1) * STAGE_B;
        const uint32_t aBase = sb + (wm * 64 + a_row) * 256;
        const uint32_t bBase = sb + OFF_BH + (wn * 64 + b_row) * 256;

#pragma unroll
        for (int ks = 0; ks < 8; ks++) {
            const int cb = ks * 2;
#pragma unroll
            for (int mt = 0; mt < 4; mt++) {
                uint32_t ad = aBase + mt * 4096 + (((cb + a_c) ^ lr) << 4);
                ldsm_x4(ah[mt], ad);
            }
#pragma unroll
            for (int nt2 = 0; nt2 < 4; nt2++) {
                uint32_t bd = bBase + nt2 * 4096 + (((cb + b_c) ^ lr) << 4);
                ldsm_x4(bh[nt2], bd);
            }
#pragma unroll
            for (int mt = 0; mt < 4; mt++) {
#pragma unroll
                for (int nt = 0; nt < 8; nt++) {
                    const uint32_t* bhf = &bh[nt >> 1][(nt & 1) * 2];
                    mma_16816(acc[mt][nt], ah[mt], bhf);
                }
            }
        }
    }

    // Epilogue. acc map: d0,d1 = (row qr, cols 2qc,2qc+1); d2,d3 = row qr+8
    const int qr = lane >> 2;
    const int qc = lane & 3;
#pragma unroll
    for (int mt = 0; mt < 4; mt++) {
        const size_t m0 = (size_t)by * 256 + wm * 64 + mt * 16 + qr;
#pragma unroll
        for (int nt = 0; nt < 8; nt++) {
            const size_t n0 = (size_t)bx * 128 + wn * 64 + nt * 8 + qc * 2;
            const float* d = acc[mt][nt];
            if (GELU) {
                __half h0 = __float2half_rn(gelu_tanh(d[0]));
                __half h1 = __float2half_rn(gelu_tanh(d[1]));
                __half h2 = __float2half_rn(gelu_tanh(d[2]));
                __half h3 = __float2half_rn(gelu_tanh(d[3]));
                *reinterpret_cast<__half2*>(Ch + m0 * N + n0)       = __halves2half2(h0, h1);
                *reinterpret_cast<__half2*>(Ch + (m0 + 8) * N + n0) = __halves2half2(h2, h3);
            } else {
                float2 v0; v0.x = d[0]; v0.y = d[1];
                float2 v1; v1.x = d[2]; v1.y = d[3];
                *reinterpret_cast<float2*>(Cf + m0 * N + n0)       = v0;
                *reinterpret_cast<float2*>(Cf + (m0 + 8) * N + n0) = v1;
            }
        }
    }
}

// ---------------------------------------------------------------------------
// Router: logits = x @ router_w (K=2048, E=8), softmax, fp16 round-trip.
// Also writes xh = fp16(x) as a side product (x is streamed anyway).
// ---------------------------------------------------------------------------
__global__ __launch_bounds__(256) void router_kernel(const float* __restrict__ x,
                                                     const float* __restrict__ rw,
                                                     float* __restrict__ probs,
                                                     __half* __restrict__ xh)
{
    int n = blockIdx.x;
    int tid = threadIdx.x;
    float acc[EEXP] = {0.f, 0.f, 0.f, 0.f, 0.f, 0.f, 0.f, 0.f};
    const float* xr = x + (size_t)n * HDIM;
    __half* xo = xh + (size_t)n * HDIM;
    for (int k = tid; k < HDIM; k += 256) {
        float xv = xr[k];
        xo[k] = __float2half_rn(xv);
        const float4* r4 = reinterpret_cast<const float4*>(rw + (size_t)k * EEXP);
        float4 a = r4[0];
        float4 b = r4[1];
        acc[0] = fmaf(xv, a.x, acc[0]); acc[1] = fmaf(xv, a.y, acc[1]);
        acc[2] = fmaf(xv, a.z, acc[2]); acc[3] = fmaf(xv, a.w, acc[3]);
        acc[4] = fmaf(xv, b.x, acc[4]); acc[5] = fmaf(xv, b.y, acc[5]);
        acc[6] = fmaf(xv, b.z, acc[6]); acc[7] = fmaf(xv, b.w, acc[7]);
    }
    __shared__ float sbuf[EEXP][256];
#pragma unroll
    for (int e = 0; e < EEXP; e++) sbuf[e][tid] = acc[e];
    __syncthreads();
    for (int s = 128; s > 0; s >>= 1) {
        if (tid < s) {
#pragma unroll
            for (int e = 0; e < EEXP; e++) sbuf[e][tid] += sbuf[e][tid + s];
        }
        __syncthreads();
    }
    if (tid == 0) {
        float l[EEXP];
        float mmax = -1e30f;
#pragma unroll
        for (int e = 0; e < EEXP; e++) { l[e] = sbuf[e][0]; mmax = fmaxf(mmax, l[e]); }
        float s = 0.f;
#pragma unroll
        for (int e = 0; e < EEXP; e++) { l[e] = expf(l[e] - mmax); s += l[e]; }
        float inv = 1.0f / s;
#pragma unroll
        for (int e = 0; e < EEXP; e++)
            probs[n * EEXP + e] = __half2float(__float2half(l[e] * inv));
    }
}

// ---------------------------------------------------------------------------
// MoE: out[n,h] += sum_e probs[n,e] * (cb[nibble]*std + mean)
// 2 tokens per 512-thread block.
// ---------------------------------------------------------------------------
__global__ __launch_bounds__(512) void moe_kernel(const int* __restrict__ nf4,
                                                  const float* __restrict__ mean,
                                                  const float* __restrict__ stdv,
                                                  const float* __restrict__ cbg,
                                                  const float* __restrict__ probs,
                                                  float* __restrict__ out)
{
    __shared__ float cb[16];
    __shared__ float pr[2][EEXP];
    const int tid = threadIdx.x;
    const int sub = tid >> 8;          // which token within block
    const int t = tid & 255;
    const int n = blockIdx.x * 2 + sub;
    if (tid < 16) cb[tid] = cbg[tid];
    if (t < EEXP) pr[sub][t] = probs[n * EEXP + t];
    __syncthreads();

    const int h0 = t * 8;
    const int b = h0 >> 9;
    float acc[8] = {0.f, 0.f, 0.f, 0.f, 0.f, 0.f, 0.f, 0.f};

    const int4* base = reinterpret_cast<const int4*>(nf4 + (size_t)n * EEXP * (HDIM / 2)) + t;
#pragma unroll
    for (int e = 0; e < EEXP; e++) {
        float p = pr[sub][e];
        float sc = p * stdv[((size_t)n * EEXP + e) * 4 + b];
        float bi = p * mean[((size_t)n * EEXP + e) * 4 + b];
        int4 v = base[e * (HDIM / 2 / 4)];
        int vs[4] = {v.x, v.y, v.z, v.w};
#pragma unroll
        for (int j = 0; j < 4; j++) {
            acc[2 * j]     += fmaf(cb[vs[j] & 15], sc, bi);
            acc[2 * j + 1] += fmaf(cb[(vs[j] >> 4) & 15], sc, bi);
        }
    }

    float4* o = reinterpret_cast<float4*>(out + (size_t)n * HDIM + h0);
    float4 o0 = o[0], o1 = o[1];
    o0.x += acc[0]; o0.y += acc[1]; o0.z += acc[2]; o0.w += acc[3];
    o1.x += acc[4]; o1.y += acc[5]; o1.z += acc[6]; o1.w += acc[7];
    o[0] = o0; o[1] = o1;
}

// ---------------------------------------------------------------------------
// Launch. inputs: 0:x 1:router_w 2:nf4 3:mean 4:std 5:codebook 6:w1 7:w2
// ---------------------------------------------------------------------------
extern "C" void kernel_launch(void* const* d_in, const int* in_sizes, int n_in,
                              void* d_out, int out_size)
{
    const float* x        = (const float*)d_in[0];
    const float* router_w = (const float*)d_in[1];
    const int*   nf4      = (const int*)d_in[2];
    const float* mean     = (const float*)d_in[3];
    const float* stdv     = (const float*)d_in[4];
    const float* codebook = (const float*)d_in[5];
    const float* w1       = (const float*)d_in[6];
    const float* w2       = (const float*)d_in[7];
    float* out = (float*)d_out;

    __half *xh, *w1h, *w2h, *h1h;
    float* probs;
    cudaGetSymbolAddress((void**)&xh,  g_xh);
    cudaGetSymbolAddress((void**)&w1h, g_w1h);
    cudaGetSymbolAddress((void**)&w2h, g_w2h);
    cudaGetSymbolAddress((void**)&h1h, g_h1h);
    cudaGetSymbolAddress((void**)&probs, g_probs);

    const int smem_bytes = 2 * STAGE_B;   // 192 KB
    cudaFuncSetAttribute(hgemm_kernel<true>,  cudaFuncAttributeMaxDynamicSharedMemorySize, smem_bytes);
    cudaFuncSetAttribute(hgemm_kernel<false>, cudaFuncAttributeMaxDynamicSharedMemorySize, smem_bytes);

    // router + x->fp16 (fused), weight transposes
    router_kernel<<<NTOK, 256>>>(x, router_w, probs, xh);
    transpose_half_kernel<<<dim3(DFF / 32, HDIM / 32), 256>>>(w1, w1h, HDIM, DFF);
    transpose_half_kernel<<<dim3(HDIM / 32, DFF / 32), 256>>>(w2, w2h, DFF, HDIM);

    // h1 = gelu(x @ w1) -> fp16   [4096 x 8192]
    hgemm_kernel<true><<<(NTOK / 256) * (DFF / 128), 256, smem_bytes>>>(
        xh, w1h, h1h, nullptr, DFF, HDIM);

    // out = h1 @ w2               [4096 x 2048]
    hgemm_kernel<false><<<(NTOK / 256) * (HDIM / 128), 256, smem_bytes>>>(
        h1h, w2h, nullptr, out, HDIM, DFF);

    // out += weighted NF4 expert mix
    moe_kernel<<<NTOK / 2, 512>>>(nf4, mean, stdv, codebook, probs, out);
}

// round 15
// speedup vs baseline: 8.5318x; 1.0081x over previous
#include <cuda_runtime.h>
#include <cuda_fp16.h>
#include <cstdint>
#include <cstddef>

// Problem constants
#define NTOK 4096   // B*L
#define HDIM 2048
#define EEXP 8
#define DFF  8192

// ---------------------------------------------------------------------------
// Scratch (device globals; no runtime allocation allowed)
// ---------------------------------------------------------------------------
__device__ __align__(256) __half g_xh[(size_t)NTOK * HDIM];
__device__ __align__(256) __half g_w1h[(size_t)DFF * HDIM];   // transposed [DFF, HDIM]
__device__ __align__(256) __half g_w2h[(size_t)HDIM * DFF];   // transposed [HDIM, DFF]
__device__ __align__(256) __half g_h1h[(size_t)NTOK * DFF];
__device__ __align__(256) float g_moe[(size_t)NTOK * HDIM];
__device__ __align__(256) float g_probs[NTOK * EEXP];

// ---------------------------------------------------------------------------
// PTX helpers (family-agnostic sm_80+ ops; tcgen05 unavailable on this toolchain)
// ---------------------------------------------------------------------------
__device__ __forceinline__ uint32_t smem_u32(const void* p) {
    uint32_t a;
    asm("{ .reg .u64 t; cvta.to.shared.u64 t, %1; cvt.u32.u64 %0, t; }" : "=r"(a) : "l"(p));
    return a;
}
__device__ __forceinline__ void cp_async16(uint32_t dst, const void* src) {
    asm volatile("cp.async.cg.shared.global [%0], [%1], 16;" :: "r"(dst), "l"(src));
}
__device__ __forceinline__ void cp_commit() {
    asm volatile("cp.async.commit_group;" ::: "memory");
}
template <int N>
__device__ __forceinline__ void cp_wait() {
    asm volatile("cp.async.wait_group %0;" :: "n"(N) : "memory");
}
__device__ __forceinline__ void ldsm_x4(uint32_t* r, uint32_t addr) {
    asm volatile("ldmatrix.sync.aligned.m8n8.x4.shared.b16 {%0,%1,%2,%3}, [%4];"
                 : "=r"(r[0]), "=r"(r[1]), "=r"(r[2]), "=r"(r[3]) : "r"(addr));
}
__device__ __forceinline__ void mma_16816(float* d, const uint32_t* a, const uint32_t* b) {
    asm volatile("mma.sync.aligned.m16n8k16.row.col.f32.f16.f16.f32 "
                 "{%0,%1,%2,%3}, {%4,%5,%6,%7}, {%8,%9}, {%0,%1,%2,%3};"
                 : "+f"(d[0]), "+f"(d[1]), "+f"(d[2]), "+f"(d[3])
                 : "r"(a[0]), "r"(a[1]), "r"(a[2]), "r"(a[3]), "r"(b[0]), "r"(b[1]));
}

// ---------------------------------------------------------------------------
// Conversion kernel: w [K,N] fp32 row-major -> oh [N,K] fp16 (transposed)
// ---------------------------------------------------------------------------
__global__ __launch_bounds__(256) void transpose_half_kernel(const float* __restrict__ w,
                                                             __half* __restrict__ oh,
                                                             int K, int N)
{
    __shared__ float t[32][33];
    const int n0 = blockIdx.x * 32;
    const int k0 = blockIdx.y * 32;
    const int tx = threadIdx.x & 31;
    const int ty = threadIdx.x >> 5;   // 0..7
#pragma unroll
    for (int r = 0; r < 4; r++) {
        int kk = ty + r * 8;
        t[kk][tx] = w[(size_t)(k0 + kk) * N + n0 + tx];
    }
    __syncthreads();
#pragma unroll
    for (int r = 0; r < 4; r++) {
        int nn = ty + r * 8;
        oh[(size_t)(n0 + nn) * K + k0 + tx] = __float2half_rn(t[tx][nn]);
    }
}

// ---------------------------------------------------------------------------
// HGEMM via mma.sync: C[M,N] = op(A @ B^T) [+ Madd]
// A [M,K] fp16, B [N,K] fp16, single product, fp32 accumulate.
// CTA tile 128x128, BK=64 (128B rows, XOR swizzle), 2-stage cp.async
// (32 KB/stage -> 64 KB/CTA), 4 warps 2(M)x2(N), warp tile 64x64,
// __launch_bounds__(128,2): TWO CTAs per SM so boundary syncs and epilogues
// of one CTA are covered by the other's MMA work. GROUP_N raster.
// GELU=true: tanh-GELU, write fp16 Ch. Else write fp32 Cf (+Madd).
// ---------------------------------------------------------------------------
#define A_T_B   16384             // A tile: 128 rows x 128 B
#define B_T_B   16384             // B tile: 128 rows x 128 B
#define STAGE_B (A_T_B + B_T_B)   // 32 KB
#define OFF_BH  A_T_B
#define GROUP_N 16

__device__ __forceinline__ float gelu_tanh(float v)
{
    float inner = 0.7978845608028654f * (v + 0.044715f * v * v * v);
    return 0.5f * v * (1.0f + tanhf(inner));
}

template <bool GELU>
__global__ __launch_bounds__(128, 2) void hgemm_kernel(const __half* __restrict__ Ah,
                                                       const __half* __restrict__ Bh,
                                                       __half* __restrict__ Ch,
                                                       float* __restrict__ Cf,
                                                       const float* __restrict__ Madd,
                                                       int N, int K)
{
    extern __shared__ __align__(1024) char smem[];
    const uint32_t sm0 = smem_u32(smem);

    const int tid = threadIdx.x;
    const int lane = tid & 31;
    const int wid = tid >> 5;
    const int wm = wid & 1;        // M warp coord (2) -> 64 rows each
    const int wn = wid >> 1;       // N warp coord (2) -> 64 cols each
    const int NK = K >> 6;         // K / 64

    // raster swizzle: consecutive CTAs walk M within a GROUP_N-wide N band
    const int tilesM = NTOK / 128;
    const int per_group = GROUP_N * tilesM;
    const int grp = blockIdx.x / per_group;
    const int rem = blockIdx.x % per_group;
    const int bx = grp * GROUP_N + (rem % GROUP_N);
    const int by = rem / GROUP_N;

    // ldmatrix lane decomposition
    const int g = lane >> 3;
    const int lr = lane & 7;
    const int a_row = ((g & 1) << 3) + lr;
    const int a_c = g >> 1;
    const int b_row = ((g >> 1) << 3) + lr;
    const int b_c = g & 1;

    // global load coords: thread t loads rows ld_r+16*it, 16B chunk ld_c
    const int ld_r = tid >> 3;     // 0..15
    const int ld_c = tid & 7;      // 16B chunk in 128B row
    const __half* gA = Ah + (size_t)(by * 128 + ld_r) * K + ld_c * 8;
    const __half* gB = Bh + (size_t)(bx * 128 + ld_r) * K + ld_c * 8;

    auto load_stage = [&](int j, int slot) {
        uint32_t sb = sm0 + slot * STAGE_B;
        size_t ko = (size_t)j * 64;   // halves
        {
            const __half* src = gA + ko;
#pragma unroll
            for (int it = 0; it < 8; it++) {          // 128 rows / 16
                int row = ld_r + it * 16;
                uint32_t d = sb + row * 128 + ((ld_c ^ (row & 7)) << 4);
                cp_async16(d, src + (size_t)it * 16 * K);
            }
        }
        {
            const __half* src = gB + ko;
            uint32_t db = sb + OFF_BH;
#pragma unroll
            for (int it = 0; it < 8; it++) {
                int row = ld_r + it * 16;
                uint32_t d = db + row * 128 + ((ld_c ^ (row & 7)) << 4);
                cp_async16(d, src + (size_t)it * 16 * K);
            }
        }
    };

    float acc[4][8][4];
#pragma unroll
    for (int mt = 0; mt < 4; mt++)
#pragma unroll
        for (int nt = 0; nt < 8; nt++)
#pragma unroll
            for (int q = 0; q < 4; q++) acc[mt][nt][q] = 0.f;

    load_stage(0, 0);
    cp_commit();

    uint32_t ah[4][4], bh[4][4];

    for (int i = 0; i < NK; i++) {
        cp_wait<0>();                 // chunk i resident
        __syncthreads();              // readers of the other slot done

        if (i + 1 < NK) {             // prefetch next chunk, overlapped w/ compute
            load_stage(i + 1, (i + 1) & 1);
            cp_commit();
        }

        const uint32_t sb = sm0 + (i & 1) * STAGE_B;
        const uint32_t aBase = sb + (wm * 64 + a_row) * 128;
        const uint32_t bBase = sb + OFF_BH + (wn * 64 + b_row) * 128;

#pragma unroll
        for (int ks = 0; ks < 4; ks++) {
            const int cb = ks * 2;
#pragma unroll
            for (int mt = 0; mt < 4; mt++) {
                uint32_t ad = aBase + mt * 2048 + (((cb + a_c) ^ lr) << 4);
                ldsm_x4(ah[mt], ad);
            }
#pragma unroll
            for (int nt2 = 0; nt2 < 4; nt2++) {
                uint32_t bd = bBase + nt2 * 2048 + (((cb + b_c) ^ lr) << 4);
                ldsm_x4(bh[nt2], bd);
            }
#pragma unroll
            for (int mt = 0; mt < 4; mt++) {
#pragma unroll
                for (int nt = 0; nt < 8; nt++) {
                    const uint32_t* bhf = &bh[nt >> 1][(nt & 1) * 2];
                    mma_16816(acc[mt][nt], ah[mt], bhf);
                }
            }
        }
    }

    // Epilogue. acc map: d0,d1 = (row qr, cols 2qc,2qc+1); d2,d3 = row qr+8
    const int qr = lane >> 2;
    const int qc = lane & 3;
#pragma unroll
    for (int mt = 0; mt < 4; mt++) {
        const size_t m0 = (size_t)by * 128 + wm * 64 + mt * 16 + qr;
#pragma unroll
        for (int nt = 0; nt < 8; nt++) {
            const size_t n0 = (size_t)bx * 128 + wn * 64 + nt * 8 + qc * 2;
            const float* d = acc[mt][nt];
            if (GELU) {
                __half h0 = __float2half_rn(gelu_tanh(d[0]));
                __half h1 = __float2half_rn(gelu_tanh(d[1]));
                __half h2 = __float2half_rn(gelu_tanh(d[2]));
                __half h3 = __float2half_rn(gelu_tanh(d[3]));
                *reinterpret_cast<__half2*>(Ch + m0 * N + n0)       = __halves2half2(h0, h1);
                *reinterpret_cast<__half2*>(Ch + (m0 + 8) * N + n0) = __halves2half2(h2, h3);
            } else {
                float2 a0 = *reinterpret_cast<const float2*>(Madd + m0 * N + n0);
                float2 a1 = *reinterpret_cast<const float2*>(Madd + (m0 + 8) * N + n0);
                float2 v0; v0.x = d[0] + a0.x; v0.y = d[1] + a0.y;
                float2 v1; v1.x = d[2] + a1.x; v1.y = d[3] + a1.y;
                *reinterpret_cast<float2*>(Cf + m0 * N + n0)       = v0;
                *reinterpret_cast<float2*>(Cf + (m0 + 8) * N + n0) = v1;
            }
        }
    }
}

// ---------------------------------------------------------------------------
// Router: logits = x @ router_w (K=2048, E=8), softmax, fp16 round-trip.
// Also writes xh = fp16(x) as a side product (x is streamed anyway).
// ---------------------------------------------------------------------------
__global__ __launch_bounds__(256) void router_kernel(const float* __restrict__ x,
                                                     const float* __restrict__ rw,
                                                     float* __restrict__ probs,
                                                     __half* __restrict__ xh)
{
    int n = blockIdx.x;
    int tid = threadIdx.x;
    float acc[EEXP] = {0.f, 0.f, 0.f, 0.f, 0.f, 0.f, 0.f, 0.f};
    const float* xr = x + (size_t)n * HDIM;
    __half* xo = xh + (size_t)n * HDIM;
    for (int k = tid; k < HDIM; k += 256) {
        float xv = xr[k];
        xo[k] = __float2half_rn(xv);
        const float4* r4 = reinterpret_cast<const float4*>(rw + (size_t)k * EEXP);
        float4 a = r4[0];
        float4 b = r4[1];
        acc[0] = fmaf(xv, a.x, acc[0]); acc[1] = fmaf(xv, a.y, acc[1]);
        acc[2] = fmaf(xv, a.z, acc[2]); acc[3] = fmaf(xv, a.w, acc[3]);
        acc[4] = fmaf(xv, b.x, acc[4]); acc[5] = fmaf(xv, b.y, acc[5]);
        acc[6] = fmaf(xv, b.z, acc[6]); acc[7] = fmaf(xv, b.w, acc[7]);
    }
    __shared__ float sbuf[EEXP][256];
#pragma unroll
    for (int e = 0; e < EEXP; e++) sbuf[e][tid] = acc[e];
    __syncthreads();
    for (int s = 128; s > 0; s >>= 1) {
        if (tid < s) {
#pragma unroll
            for (int e = 0; e < EEXP; e++) sbuf[e][tid] += sbuf[e][tid + s];
        }
        __syncthreads();
    }
    if (tid == 0) {
        float l[EEXP];
        float mmax = -1e30f;
#pragma unroll
        for (int e = 0; e < EEXP; e++) { l[e] = sbuf[e][0]; mmax = fmaxf(mmax, l[e]); }
        float s = 0.f;
#pragma unroll
        for (int e = 0; e < EEXP; e++) { l[e] = expf(l[e] - mmax); s += l[e]; }
        float inv = 1.0f / s;
#pragma unroll
        for (int e = 0; e < EEXP; e++)
            probs[n * EEXP + e] = __half2float(__float2half(l[e] * inv));
    }
}

// ---------------------------------------------------------------------------
// MoE: moe_out[n,h] = sum_e probs[n,e] * (cb[nibble]*std + mean)
// Writes its own buffer (added in GEMM2 epilogue). 2 tokens / 512-thr block.
// ---------------------------------------------------------------------------
__global__ __launch_bounds__(512) void moe_kernel(const int* __restrict__ nf4,
                                                  const float* __restrict__ mean,
                                                  const float* __restrict__ stdv,
                                                  const float* __restrict__ cbg,
                                                  const float* __restrict__ probs,
                                                  float* __restrict__ moe_out)
{
    __shared__ float cb[16];
    __shared__ float pr[2][EEXP];
    const int tid = threadIdx.x;
    const int sub = tid >> 8;          // which token within block
    const int t = tid & 255;
    const int n = blockIdx.x * 2 + sub;
    if (tid < 16) cb[tid] = cbg[tid];
    if (t < EEXP) pr[sub][t] = probs[n * EEXP + t];
    __syncthreads();

    const int h0 = t * 8;
    const int b = h0 >> 9;
    float acc[8] = {0.f, 0.f, 0.f, 0.f, 0.f, 0.f, 0.f, 0.f};

    const int4* base = reinterpret_cast<const int4*>(nf4 + (size_t)n * EEXP * (HDIM / 2)) + t;
#pragma unroll
    for (int e = 0; e < EEXP; e++) {
        float p = pr[sub][e];
        float sc = p * stdv[((size_t)n * EEXP + e) * 4 + b];
        float bi = p * mean[((size_t)n * EEXP + e) * 4 + b];
        int4 v = base[e * (HDIM / 2 / 4)];
        int vs[4] = {v.x, v.y, v.z, v.w};
#pragma unroll
        for (int j = 0; j < 4; j++) {
            acc[2 * j]     += fmaf(cb[vs[j] & 15], sc, bi);
            acc[2 * j + 1] += fmaf(cb[(vs[j] >> 4) & 15], sc, bi);
        }
    }

    float4* o = reinterpret_cast<float4*>(moe_out + (size_t)n * HDIM + h0);
    float4 o0, o1;
    o0.x = acc[0]; o0.y = acc[1]; o0.z = acc[2]; o0.w = acc[3];
    o1.x = acc[4]; o1.y = acc[5]; o1.z = acc[6]; o1.w = acc[7];
    o[0] = o0; o[1] = o1;
}

// ---------------------------------------------------------------------------
// Launch (single stream — graph-capture safe).
// inputs: 0:x 1:router_w 2:nf4 3:mean 4:std 5:codebook 6:w1 7:w2
// ---------------------------------------------------------------------------
extern "C" void kernel_launch(void* const* d_in, const int* in_sizes, int n_in,
                              void* d_out, int out_size)
{
    const float* x        = (const float*)d_in[0];
    const float* router_w = (const float*)d_in[1];
    const int*   nf4      = (const int*)d_in[2];
    const float* mean     = (const float*)d_in[3];
    const float* stdv     = (const float*)d_in[4];
    const float* codebook = (const float*)d_in[5];
    const float* w1       = (const float*)d_in[6];
    const float* w2       = (const float*)d_in[7];
    float* out = (float*)d_out;

    __half *xh, *w1h, *w2h, *h1h;
    float *probs, *moebuf;
    cudaGetSymbolAddress((void**)&xh,  g_xh);
    cudaGetSymbolAddress((void**)&w1h, g_w1h);
    cudaGetSymbolAddress((void**)&w2h, g_w2h);
    cudaGetSymbolAddress((void**)&h1h, g_h1h);
    cudaGetSymbolAddress((void**)&probs, g_probs);
    cudaGetSymbolAddress((void**)&moebuf, g_moe);

    const int smem_bytes = 2 * STAGE_B;   // 64 KB
    cudaFuncSetAttribute(hgemm_kernel<true>,  cudaFuncAttributeMaxDynamicSharedMemorySize, smem_bytes);
    cudaFuncSetAttribute(hgemm_kernel<false>, cudaFuncAttributeMaxDynamicSharedMemorySize, smem_bytes);

    // router (+ x->fp16), weight transposes, moe mix into its own buffer
    router_kernel<<<NTOK, 256>>>(x, router_w, probs, xh);
    transpose_half_kernel<<<dim3(DFF / 32, HDIM / 32), 256>>>(w1, w1h, HDIM, DFF);
    transpose_half_kernel<<<dim3(HDIM / 32, DFF / 32), 256>>>(w2, w2h, DFF, HDIM);
    moe_kernel<<<NTOK / 2, 512>>>(nf4, mean, stdv, codebook, probs, moebuf);

    // h1 = gelu(x @ w1) -> fp16   [4096 x 8192]  (32 x 64 tiles = 2048 CTAs)
    hgemm_kernel<true><<<(NTOK / 128) * (DFF / 128), 128, smem_bytes>>>(
        xh, w1h, h1h, nullptr, nullptr, DFF, HDIM);

    // out = h1 @ w2 + moe         [4096 x 2048]  (32 x 16 tiles = 512 CTAs)
    hgemm_kernel<false><<<(NTOK / 128) * (HDIM / 128), 128, smem_bytes>>>(
        h1h, w2h, nullptr, out, moebuf, HDIM, DFF);
}

// round 16
// speedup vs baseline: 9.4687x; 1.1098x over previous
#include <cuda_runtime.h>
#include <cuda_fp16.h>
#include <cstdint>
#include <cstddef>

// Problem constants
#define NTOK 4096   // B*L
#define HDIM 2048
#define EEXP 8
#define DFF  8192

// ---------------------------------------------------------------------------
// Scratch (device globals; no runtime allocation allowed)
// ---------------------------------------------------------------------------
__device__ __align__(256) __half g_xh[(size_t)NTOK * HDIM];
__device__ __align__(256) __half g_w1h[(size_t)DFF * HDIM];   // transposed [DFF, HDIM]
__device__ __align__(256) __half g_w2h[(size_t)HDIM * DFF];   // transposed [HDIM, DFF]
__device__ __align__(256) __half g_h1h[(size_t)NTOK * DFF];
__device__ __align__(256) float g_moe[(size_t)NTOK * HDIM];

// ---------------------------------------------------------------------------
// PTX helpers (family-agnostic sm_80+ ops; tcgen05 unavailable on this toolchain)
// ---------------------------------------------------------------------------
__device__ __forceinline__ uint32_t smem_u32(const void* p) {
    uint32_t a;
    asm("{ .reg .u64 t; cvta.to.shared.u64 t, %1; cvt.u32.u64 %0, t; }" : "=r"(a) : "l"(p));
    return a;
}
__device__ __forceinline__ void cp_async16(uint32_t dst, const void* src) {
    asm volatile("cp.async.cg.shared.global [%0], [%1], 16;" :: "r"(dst), "l"(src));
}
__device__ __forceinline__ void cp_commit() {
    asm volatile("cp.async.commit_group;" ::: "memory");
}
template <int N>
__device__ __forceinline__ void cp_wait() {
    asm volatile("cp.async.wait_group %0;" :: "n"(N) : "memory");
}
__device__ __forceinline__ void ldsm_x4(uint32_t* r, uint32_t addr) {
    asm volatile("ldmatrix.sync.aligned.m8n8.x4.shared.b16 {%0,%1,%2,%3}, [%4];"
                 : "=r"(r[0]), "=r"(r[1]), "=r"(r[2]), "=r"(r[3]) : "r"(addr));
}
__device__ __forceinline__ void mma_16816(float* d, const uint32_t* a, const uint32_t* b) {
    asm volatile("mma.sync.aligned.m16n8k16.row.col.f32.f16.f16.f32 "
                 "{%0,%1,%2,%3}, {%4,%5,%6,%7}, {%8,%9}, {%0,%1,%2,%3};"
                 : "+f"(d[0]), "+f"(d[1]), "+f"(d[2]), "+f"(d[3])
                 : "r"(a[0]), "r"(a[1]), "r"(a[2]), "r"(a[3]), "r"(b[0]), "r"(b[1]));
}

// ---------------------------------------------------------------------------
// Conversion kernel: w [K,N] fp32 row-major -> oh [N,K] fp16 (transposed)
// ---------------------------------------------------------------------------
__global__ __launch_bounds__(256) void transpose_half_kernel(const float* __restrict__ w,
                                                             __half* __restrict__ oh,
                                                             int K, int N)
{
    __shared__ float t[32][33];
    const int n0 = blockIdx.x * 32;
    const int k0 = blockIdx.y * 32;
    const int tx = threadIdx.x & 31;
    const int ty = threadIdx.x >> 5;   // 0..7
#pragma unroll
    for (int r = 0; r < 4; r++) {
        int kk = ty + r * 8;
        t[kk][tx] = w[(size_t)(k0 + kk) * N + n0 + tx];
    }
    __syncthreads();
#pragma unroll
    for (int r = 0; r < 4; r++) {
        int nn = ty + r * 8;
        oh[(size_t)(n0 + nn) * K + k0 + tx] = __float2half_rn(t[tx][nn]);
    }
}

// ---------------------------------------------------------------------------
// HGEMM via mma.sync: C[M,N] = op(A @ B^T) [+ Madd]
// A [M,K] fp16, B [N,K] fp16, single product, fp32 accumulate.
// CTA tile 128x64, BK=64 (128B rows, XOR swizzle), 2-stage cp.async
// (24 KB/stage -> 48 KB/CTA), 4 warps 2(M)x2(N), warp tile 64x32,
// __launch_bounds__(128,4): FOUR CTAs per SM = 16 warps = 4/SMSP to cover
// ldsm latency and issue gaps (prior configs were all stuck at 8 warps/SM).
// GELU=true: tanh-GELU, write fp16 Ch. Else write fp32 Cf (+Madd).
// ---------------------------------------------------------------------------
#define A_T_B   16384             // A tile: 128 rows x 128 B
#define B_T_B   8192              // B tile: 64 rows x 128 B
#define STAGE_B (A_T_B + B_T_B)   // 24 KB
#define OFF_BH  A_T_B
#define GROUP_N 16

__device__ __forceinline__ float gelu_tanh(float v)
{
    float inner = 0.7978845608028654f * (v + 0.044715f * v * v * v);
    return 0.5f * v * (1.0f + tanhf(inner));
}

template <bool GELU>
__global__ __launch_bounds__(128, 4) void hgemm_kernel(const __half* __restrict__ Ah,
                                                       const __half* __restrict__ Bh,
                                                       __half* __restrict__ Ch,
                                                       float* __restrict__ Cf,
                                                       const float* __restrict__ Madd,
                                                       int N, int K)
{
    extern __shared__ __align__(1024) char smem[];
    const uint32_t sm0 = smem_u32(smem);

    const int tid = threadIdx.x;
    const int lane = tid & 31;
    const int wid = tid >> 5;
    const int wm = wid & 1;        // M warp coord (2) -> 64 rows each
    const int wn = wid >> 1;       // N warp coord (2) -> 32 cols each
    const int NK = K >> 6;         // K / 64

    // raster swizzle: consecutive CTAs walk M within a GROUP_N-wide N band
    const int tilesM = NTOK / 128;
    const int per_group = GROUP_N * tilesM;
    const int grp = blockIdx.x / per_group;
    const int rem = blockIdx.x % per_group;
    const int bx = grp * GROUP_N + (rem % GROUP_N);
    const int by = rem / GROUP_N;

    // ldmatrix lane decomposition
    const int g = lane >> 3;
    const int lr = lane & 7;
    const int a_row = ((g & 1) << 3) + lr;
    const int a_c = g >> 1;
    const int b_row = ((g >> 1) << 3) + lr;
    const int b_c = g & 1;

    // global load coords: thread t loads rows ld_r+16*it, 16B chunk ld_c
    const int ld_r = tid >> 3;     // 0..15
    const int ld_c = tid & 7;      // 16B chunk in 128B row
    const __half* gA = Ah + (size_t)(by * 128 + ld_r) * K + ld_c * 8;
    const __half* gB = Bh + (size_t)(bx * 64 + ld_r) * K + ld_c * 8;

    auto load_stage = [&](int j, int slot) {
        uint32_t sb = sm0 + slot * STAGE_B;
        size_t ko = (size_t)j * 64;   // halves
        {
            const __half* src = gA + ko;
#pragma unroll
            for (int it = 0; it < 8; it++) {          // 128 rows / 16
                int row = ld_r + it * 16;
                uint32_t d = sb + row * 128 + ((ld_c ^ (row & 7)) << 4);
                cp_async16(d, src + (size_t)it * 16 * K);
            }
        }
        {
            const __half* src = gB + ko;
            uint32_t db = sb + OFF_BH;
#pragma unroll
            for (int it = 0; it < 4; it++) {          // 64 rows / 16
                int row = ld_r + it * 16;
                uint32_t d = db + row * 128 + ((ld_c ^ (row & 7)) << 4);
                cp_async16(d, src + (size_t)it * 16 * K);
            }
        }
    };

    float acc[4][4][4];
#pragma unroll
    for (int mt = 0; mt < 4; mt++)
#pragma unroll
        for (int nt = 0; nt < 4; nt++)
#pragma unroll
            for (int q = 0; q < 4; q++) acc[mt][nt][q] = 0.f;

    load_stage(0, 0);
    cp_commit();

    uint32_t ah[4][4], bh[2][4];

    for (int i = 0; i < NK; i++) {
        cp_wait<0>();                 // chunk i resident
        __syncthreads();              // readers of the other slot done

        if (i + 1 < NK) {             // prefetch next chunk, overlapped w/ compute
            load_stage(i + 1, (i + 1) & 1);
            cp_commit();
        }

        const uint32_t sb = sm0 + (i & 1) * STAGE_B;
        const uint32_t aBase = sb + (wm * 64 + a_row) * 128;
        const uint32_t bBase = sb + OFF_BH + (wn * 32 + b_row) * 128;

#pragma unroll
        for (int ks = 0; ks < 4; ks++) {
            const int cb = ks * 2;
#pragma unroll
            for (int mt = 0; mt < 4; mt++) {
                uint32_t ad = aBase + mt * 2048 + (((cb + a_c) ^ lr) << 4);
                ldsm_x4(ah[mt], ad);
            }
#pragma unroll
            for (int nt2 = 0; nt2 < 2; nt2++) {
                uint32_t bd = bBase + nt2 * 2048 + (((cb + b_c) ^ lr) << 4);
                ldsm_x4(bh[nt2], bd);
            }
#pragma unroll
            for (int mt = 0; mt < 4; mt++) {
#pragma unroll
                for (int nt = 0; nt < 4; nt++) {
                    const uint32_t* bhf = &bh[nt >> 1][(nt & 1) * 2];
                    mma_16816(acc[mt][nt], ah[mt], bhf);
                }
            }
        }
    }

    // Epilogue. acc map: d0,d1 = (row qr, cols 2qc,2qc+1); d2,d3 = row qr+8
    const int qr = lane >> 2;
    const int qc = lane & 3;
#pragma unroll
    for (int mt = 0; mt < 4; mt++) {
        const size_t m0 = (size_t)by * 128 + wm * 64 + mt * 16 + qr;
#pragma unroll
        for (int nt = 0; nt < 4; nt++) {
            const size_t n0 = (size_t)bx * 64 + wn * 32 + nt * 8 + qc * 2;
            const float* d = acc[mt][nt];
            if (GELU) {
                __half h0 = __float2half_rn(gelu_tanh(d[0]));
                __half h1 = __float2half_rn(gelu_tanh(d[1]));
                __half h2 = __float2half_rn(gelu_tanh(d[2]));
                __half h3 = __float2half_rn(gelu_tanh(d[3]));
                *reinterpret_cast<__half2*>(Ch + m0 * N + n0)       = __halves2half2(h0, h1);
                *reinterpret_cast<__half2*>(Ch + (m0 + 8) * N + n0) = __halves2half2(h2, h3);
            } else {
                float2 a0 = *reinterpret_cast<const float2*>(Madd + m0 * N + n0);
                float2 a1 = *reinterpret_cast<const float2*>(Madd + (m0 + 8) * N + n0);
                float2 v0; v0.x = d[0] + a0.x; v0.y = d[1] + a0.y;
                float2 v1; v1.x = d[2] + a1.x; v1.y = d[3] + a1.y;
                *reinterpret_cast<float2*>(Cf + m0 * N + n0)       = v0;
                *reinterpret_cast<float2*>(Cf + (m0 + 8) * N + n0) = v1;
            }
        }
    }
}

// ---------------------------------------------------------------------------
// Fused router + MoE: one block per token.
// Part 1: logits = x@rw, softmax (fp32), fp16 round-trip -> smem probs.
//         Also writes xh = fp16(x).
// Part 2: moe_out[n,h] = sum_e probs[e] * (cb[nibble]*std + mean).
// ---------------------------------------------------------------------------
__global__ __launch_bounds__(256) void router_moe_kernel(const float* __restrict__ x,
                                                         const float* __restrict__ rw,
                                                         const int* __restrict__ nf4,
                                                         const float* __restrict__ mean,
                                                         const float* __restrict__ stdv,
                                                         const float* __restrict__ cbg,
                                                         __half* __restrict__ xh,
                                                         float* __restrict__ moe_out)
{
    const int n = blockIdx.x;
    const int tid = threadIdx.x;
    __shared__ float sbuf[EEXP][256];
    __shared__ float pr[EEXP];
    __shared__ float cb[16];
    if (tid < 16) cb[tid] = cbg[tid];

    // --- router ---
    float acc[EEXP] = {0.f, 0.f, 0.f, 0.f, 0.f, 0.f, 0.f, 0.f};
    const float* xr = x + (size_t)n * HDIM;
    __half* xo = xh + (size_t)n * HDIM;
    for (int k = tid; k < HDIM; k += 256) {
        float xv = xr[k];
        xo[k] = __float2half_rn(xv);
        const float4* r4 = reinterpret_cast<const float4*>(rw + (size_t)k * EEXP);
        float4 a = r4[0];
        float4 b = r4[1];
        acc[0] = fmaf(xv, a.x, acc[0]); acc[1] = fmaf(xv, a.y, acc[1]);
        acc[2] = fmaf(xv, a.z, acc[2]); acc[3] = fmaf(xv, a.w, acc[3]);
        acc[4] = fmaf(xv, b.x, acc[4]); acc[5] = fmaf(xv, b.y, acc[5]);
        acc[6] = fmaf(xv, b.z, acc[6]); acc[7] = fmaf(xv, b.w, acc[7]);
    }
#pragma unroll
    for (int e = 0; e < EEXP; e++) sbuf[e][tid] = acc[e];
    __syncthreads();
    for (int s = 128; s > 0; s >>= 1) {
        if (tid < s) {
#pragma unroll
            for (int e = 0; e < EEXP; e++) sbuf[e][tid] += sbuf[e][tid + s];
        }
        __syncthreads();
    }
    if (tid == 0) {
        float l[EEXP];
        float mmax = -1e30f;
#pragma unroll
        for (int e = 0; e < EEXP; e++) { l[e] = sbuf[e][0]; mmax = fmaxf(mmax, l[e]); }
        float s = 0.f;
#pragma unroll
        for (int e = 0; e < EEXP; e++) { l[e] = expf(l[e] - mmax); s += l[e]; }
        float inv = 1.0f / s;
#pragma unroll
        for (int e = 0; e < EEXP; e++)
            pr[e] = __half2float(__float2half(l[e] * inv));
    }
    __syncthreads();

    // --- moe mix ---
    const int h0 = tid * 8;
    const int b = h0 >> 9;
    float macc[8] = {0.f, 0.f, 0.f, 0.f, 0.f, 0.f, 0.f, 0.f};
    const int4* base = reinterpret_cast<const int4*>(nf4 + (size_t)n * EEXP * (HDIM / 2)) + tid;
#pragma unroll
    for (int e = 0; e < EEXP; e++) {
        float p = pr[e];
        float sc = p * stdv[((size_t)n * EEXP + e) * 4 + b];
        float bi = p * mean[((size_t)n * EEXP + e) * 4 + b];
        int4 v = base[e * (HDIM / 2 / 4)];
        int vs[4] = {v.x, v.y, v.z, v.w};
#pragma unroll
        for (int j = 0; j < 4; j++) {
            macc[2 * j]     += fmaf(cb[vs[j] & 15], sc, bi);
            macc[2 * j + 1] += fmaf(cb[(vs[j] >> 4) & 15], sc, bi);
        }
    }
    float4* o = reinterpret_cast<float4*>(moe_out + (size_t)n * HDIM + h0);
    float4 o0, o1;
    o0.x = macc[0]; o0.y = macc[1]; o0.z = macc[2]; o0.w = macc[3];
    o1.x = macc[4]; o1.y = macc[5]; o1.z = macc[6]; o1.w = macc[7];
    o[0] = o0; o[1] = o1;
}

// ---------------------------------------------------------------------------
// Launch (single stream — graph-capture safe).
// inputs: 0:x 1:router_w 2:nf4 3:mean 4:std 5:codebook 6:w1 7:w2
// ---------------------------------------------------------------------------
extern "C" void kernel_launch(void* const* d_in, const int* in_sizes, int n_in,
                              void* d_out, int out_size)
{
    const float* x        = (const float*)d_in[0];
    const float* router_w = (const float*)d_in[1];
    const int*   nf4      = (const int*)d_in[2];
    const float* mean     = (const float*)d_in[3];
    const float* stdv     = (const float*)d_in[4];
    const float* codebook = (const float*)d_in[5];
    const float* w1       = (const float*)d_in[6];
    const float* w2       = (const float*)d_in[7];
    float* out = (float*)d_out;

    __half *xh, *w1h, *w2h, *h1h;
    float *moebuf;
    cudaGetSymbolAddress((void**)&xh,  g_xh);
    cudaGetSymbolAddress((void**)&w1h, g_w1h);
    cudaGetSymbolAddress((void**)&w2h, g_w2h);
    cudaGetSymbolAddress((void**)&h1h, g_h1h);
    cudaGetSymbolAddress((void**)&moebuf, g_moe);

    const int smem_bytes = 2 * STAGE_B;   // 48 KB
    cudaFuncSetAttribute(hgemm_kernel<true>,  cudaFuncAttributeMaxDynamicSharedMemorySize, smem_bytes);
    cudaFuncSetAttribute(hgemm_kernel<false>, cudaFuncAttributeMaxDynamicSharedMemorySize, smem_bytes);

    // fused router + x->fp16 + moe mix; weight transposes
    router_moe_kernel<<<NTOK, 256>>>(x, router_w, nf4, mean, stdv, codebook, xh, moebuf);
    transpose_half_kernel<<<dim3(DFF / 32, HDIM / 32), 256>>>(w1, w1h, HDIM, DFF);
    transpose_half_kernel<<<dim3(HDIM / 32, DFF / 32), 256>>>(w2, w2h, DFF, HDIM);

    // h1 = gelu(x @ w1) -> fp16   [4096 x 8192]  (32 M x 128 N tiles = 4096 CTAs)
    hgemm_kernel<true><<<(NTOK / 128) * (DFF / 64), 128, smem_bytes>>>(
        xh, w1h, h1h, nullptr, nullptr, DFF, HDIM);

    // out = h1 @ w2 + moe         [4096 x 2048]  (32 x 32 tiles = 1024 CTAs)
    hgemm_kernel<false><<<(NTOK / 128) * (HDIM / 64), 128, smem_bytes>>>(
        h1h, w2h, nullptr, out, moebuf, HDIM, DFF);
}